// round 14
// baseline (speedup 1.0000x reference)
#include <cuda_runtime.h>
#include <cuda_fp16.h>
#include <cstdint>
#include <cstdio>

#define SEQ   2048
#define HID   2560
#define QD    4096      // 32 heads * 128
#define KVD   1024      // 8 heads * 128
#define QKVD  6144      // QD + 2*KVD
#define HD    128
#define NQH   32
#define NKVH  8

// ---------------------------------------------------------------------------
// Scratch (device globals; no allocation allowed)
// ---------------------------------------------------------------------------
__device__ float g_qkv[(size_t)SEQ * QKVD];   // [s, 6144]: Q | K | V (fp32)
__device__ float g_part[(size_t)SEQ * HID];   // split-K partial for Wo gemm

// fp16 operand buffers
__device__ __half g_hid_h[(size_t)SEQ * HID];     // hidden (A of QKV gemm)
__device__ __half g_wqkv_h[(size_t)QKVD * HID];   // Wq|Wk|Wv stacked (B)
__device__ __half g_wo_h[(size_t)HID * QD];       // Wo (B)
__device__ __half g_ao_h[(size_t)SEQ * QD];       // attn out (A of Wo gemm)

// attention operands, [head][seq][128]
__device__ __half g_qh[(size_t)NQH * SEQ * HD];   // Q (scale*log2e folded)
__device__ __half g_kh[(size_t)NKVH * SEQ * HD];  // K
__device__ __half g_vh[(size_t)NKVH * SEQ * HD];  // V

// ---------------------------------------------------------------------------
// PTX helpers
// ---------------------------------------------------------------------------
__device__ __forceinline__ uint32_t smem_u32(const void* p) {
    uint32_t a;
    asm("{ .reg .u64 t; cvta.to.shared.u64 t, %1; cvt.u32.u64 %0, t; }" : "=r"(a) : "l"(p));
    return a;
}
__device__ __forceinline__ void cpa16(uint32_t s, const void* g) {
    asm volatile("cp.async.cg.shared.global [%0], [%1], 16;" :: "r"(s), "l"(g));
}
__device__ __forceinline__ void cpa_commit() {
    asm volatile("cp.async.commit_group;" ::: "memory");
}
__device__ __forceinline__ void cpa_wait1() {
    asm volatile("cp.async.wait_group 1;" ::: "memory");
}
__device__ __forceinline__ void cpa_wait0() {
    asm volatile("cp.async.wait_group 0;" ::: "memory");
}
__device__ __forceinline__ void ldm_x4(uint32_t* r, uint32_t addr) {
    asm volatile("ldmatrix.sync.aligned.m8n8.x4.shared.b16 {%0,%1,%2,%3}, [%4];"
                 : "=r"(r[0]), "=r"(r[1]), "=r"(r[2]), "=r"(r[3]) : "r"(addr));
}
__device__ __forceinline__ void ldm_x4_t(uint32_t* r, uint32_t addr) {
    asm volatile("ldmatrix.sync.aligned.m8n8.x4.trans.shared.b16 {%0,%1,%2,%3}, [%4];"
                 : "=r"(r[0]), "=r"(r[1]), "=r"(r[2]), "=r"(r[3]) : "r"(addr));
}
__device__ __forceinline__ void mma_f16(float* c, const uint32_t* a, const uint32_t* b) {
    asm volatile(
        "mma.sync.aligned.m16n8k16.row.col.f32.f16.f16.f32 "
        "{%0,%1,%2,%3}, {%4,%5,%6,%7}, {%8,%9}, {%0,%1,%2,%3};"
        : "+f"(c[0]), "+f"(c[1]), "+f"(c[2]), "+f"(c[3])
        : "r"(a[0]), "r"(a[1]), "r"(a[2]), "r"(a[3]), "r"(b[0]), "r"(b[1]));
}
__device__ __forceinline__ uint32_t ex2_h2(float a, float b) {
    __half2 t = __floats2half2_rn(a, b);
    uint32_t in = *(uint32_t*)&t, out;
    asm("ex2.approx.f16x2 %0, %1;" : "=r"(out) : "r"(in));
    return out;
}

// ---------------------------------------------------------------------------
// fused fp32 -> fp16 conversion over all 5 input regions (one launch)
// ---------------------------------------------------------------------------
__global__ __launch_bounds__(256)
void cvt_all(const float* __restrict__ hid, const float* __restrict__ wq,
             const float* __restrict__ wk, const float* __restrict__ wv,
             const float* __restrict__ wo) {
    size_t i = ((size_t)blockIdx.x * blockDim.x + threadIdx.x) * 4;
    const size_t n0 = (size_t)SEQ * HID;
    const size_t n1 = (size_t)QD * HID;
    const size_t n2 = (size_t)KVD * HID;
    const size_t n4 = (size_t)HID * QD;

    const float* src;
    __half* dst;
    if (i < n0)                { src = hid; dst = g_hid_h + i; }
    else if ((i -= n0) < n1)   { src = wq;  dst = g_wqkv_h + i; }
    else if ((i -= n1) < n2)   { src = wk;  dst = g_wqkv_h + n1 + i; }
    else if ((i -= n2) < n2)   { src = wv;  dst = g_wqkv_h + n1 + n2 + i; }
    else if ((i -= n2) < n4)   { src = wo;  dst = g_wo_h + i; }
    else return;

    float4 x = *(const float4*)(src + i);
    *(__half2*)(dst)     = __floats2half2_rn(x.x, x.y);
    *(__half2*)(dst + 2) = __floats2half2_rn(x.z, x.w);
}

// elementwise add for split-K reduction: dst += src
__global__ __launch_bounds__(256)
void add_kernel(float* __restrict__ dst, const float* __restrict__ src, int n) {
    int i = (blockIdx.x * blockDim.x + threadIdx.x) * 4;
    if (i >= n) return;
    float4 a = *(float4*)(dst + i);
    float4 b = *(const float4*)(src + i);
    a.x += b.x; a.y += b.y; a.z += b.z; a.w += b.w;
    *(float4*)(dst + i) = a;
}

// ---------------------------------------------------------------------------
// mma.sync fp16 GEMM (NT): C[m,n] = sum_{k0<=k<k0+klen} A[m,k]*B[n,k].
// CTA 128x128, 4 warps (2x2), warp tile 64x64 (LDSM/MMA ratio 0.25).
// BK=64, 3-stage cp.async ring, one barrier per chunk.
// ---------------------------------------------------------------------------
#define BK 64
#define LDS_STR 72                    // 64 halves + 8 pad (conflict-free)
#define TILE_H (128 * LDS_STR)
#define STAGE_H (2 * TILE_H)          // A | B
#define GEMM_SMEM (3 * STAGE_H * 2)   // 110592 B

__global__ __launch_bounds__(128, 2)
void gemm_mma(const __half* __restrict__ Ah, const __half* __restrict__ Bh,
              float* __restrict__ C, int K, int k0, int klen, int ldc) {
    extern __shared__ __half smem[];
    const uint32_t sbase = smem_u32(smem);

    const int tid  = threadIdx.x;
    const int warp = tid >> 5;
    const int lane = tid & 31;
    const int wm   = warp & 1;        // m-offset wm*64
    const int wn   = warp >> 1;       // n-offset wn*64
    const int bx = blockIdx.x, by = blockIdx.y;

    const __half* gA = Ah + (size_t)(by * 128) * K + k0;
    const __half* gB = Bh + (size_t)(bx * 128) * K + k0;

    float acc[4][8][4];
    #pragma unroll
    for (int mi = 0; mi < 4; mi++)
        #pragma unroll
        for (int j = 0; j < 8; j++)
            #pragma unroll
            for (int t = 0; t < 4; t++) acc[mi][j][t] = 0.0f;

    const int nchunk = klen / BK;
    const int r0 = tid >> 1;              // 0..63
    const int ch0 = (tid & 1) * 32;       // half-offset 0 or 32

    auto load_stage = [&](int c, int s) {
        const size_t koff = (size_t)c * BK;
        uint32_t dst = sbase + (uint32_t)(s * STAGE_H) * 2;
        const __half* a0 = gA + (size_t)r0 * K + koff + ch0;
        const __half* a1 = gA + (size_t)(r0 + 64) * K + koff + ch0;
        const __half* b0 = gB + (size_t)r0 * K + koff + ch0;
        const __half* b1 = gB + (size_t)(r0 + 64) * K + koff + ch0;
        uint32_t dA0 = dst + (uint32_t)(r0 * LDS_STR + ch0) * 2;
        uint32_t dA1 = dst + (uint32_t)((r0 + 64) * LDS_STR + ch0) * 2;
        uint32_t dB0 = dA0 + (uint32_t)TILE_H * 2;
        uint32_t dB1 = dA1 + (uint32_t)TILE_H * 2;
        #pragma unroll
        for (int q = 0; q < 4; q++) {
            cpa16(dA0 + q * 16, a0 + q * 8);
            cpa16(dA1 + q * 16, a1 + q * 8);
            cpa16(dB0 + q * 16, b0 + q * 8);
            cpa16(dB1 + q * 16, b1 + q * 8);
        }
    };

    const int a_row = (lane & 7) + ((lane >> 3) & 1) * 8;
    const int a_kof = (lane >> 4) * 8;
    const int b_mat = lane >> 3;
    const int b_row = lane & 7;
    const int b_kof = (b_mat & 1) * 8;
    const int b_jof = (b_mat >> 1);

    // prologue: 2-deep prefetch
    load_stage(0, 0);
    cpa_commit();
    load_stage(1, 1);
    cpa_commit();

    int stage = 0;
    for (int c = 0; c < nchunk; c++) {
        if (c == nchunk - 1) cpa_wait0(); else cpa_wait1();
        __syncthreads();
        if (c + 2 < nchunk) {
            int s2 = stage + 2; if (s2 >= 3) s2 -= 3;
            load_stage(c + 2, s2);
            cpa_commit();
        }

        const uint32_t st = sbase + (uint32_t)(stage * STAGE_H) * 2;
        const uint32_t sA = st;
        const uint32_t sB = st + (uint32_t)TILE_H * 2;

        #pragma unroll
        for (int ks = 0; ks < 4; ks++) {
            uint32_t ah[4][4];
            #pragma unroll
            for (int mi = 0; mi < 4; mi++) {
                int m_local = wm * 64 + mi * 16 + a_row;
                uint32_t off = (uint32_t)(m_local * LDS_STR + ks * 16 + a_kof) * 2;
                ldm_x4(ah[mi], sA + off);
            }
            #pragma unroll
            for (int nj = 0; nj < 4; nj++) {
                int n_local = wn * 64 + (nj * 2 + b_jof) * 8 + b_row;
                uint32_t off = (uint32_t)(n_local * LDS_STR + ks * 16 + b_kof) * 2;
                uint32_t rh[4];
                ldm_x4(rh, sB + off);
                const int j0 = nj * 2, j1 = nj * 2 + 1;
                #pragma unroll
                for (int mi = 0; mi < 4; mi++) {
                    mma_f16(acc[mi][j0], ah[mi], rh);
                    mma_f16(acc[mi][j1], ah[mi], rh + 2);
                }
            }
        }
        if (++stage == 3) stage = 0;
    }

    const int gid = lane >> 2;
    const int tgc = (lane & 3) * 2;
    #pragma unroll
    for (int mi = 0; mi < 4; mi++) {
        int row = by * 128 + wm * 64 + mi * 16 + gid;
        #pragma unroll
        for (int j = 0; j < 8; j++) {
            int col = bx * 128 + wn * 64 + j * 8 + tgc;
            float2 v0 = {acc[mi][j][0], acc[mi][j][1]};
            float2 v1 = {acc[mi][j][2], acc[mi][j][3]};
            *(float2*)(C + (size_t)row * ldc + col)       = v0;
            *(float2*)(C + (size_t)(row + 8) * ldc + col) = v1;
        }
    }
}

// ---------------------------------------------------------------------------
// RMSNorm + RoPE, fp32 g_qkv -> fp16 buffers, [h][s][d] layout.
// ---------------------------------------------------------------------------
__global__ __launch_bounds__(256)
void rms_rope_kernel(const float* __restrict__ cosb, const float* __restrict__ sinb,
                     const float* __restrict__ qw, const float* __restrict__ kw) {
    int gw = (blockIdx.x * blockDim.x + threadIdx.x) >> 5;
    int lane = threadIdx.x & 31;
    if (gw >= SEQ * 48) return;
    int s = gw / 48;
    int h = gw % 48;
    int d = lane * 4;

    float4 out;
    __half* dsingle;

    if (h < 40) {
        const float* base;
        const float* w;
        if (h < NQH) {
            base = g_qkv + (size_t)s * QKVD + h * HD;
            w = qw;
            dsingle = g_qh + ((size_t)h * SEQ + s) * HD;
        } else {
            int kh = h - NQH;
            base = g_qkv + (size_t)s * QKVD + QD + kh * HD;
            w = kw;
            dsingle = g_kh + ((size_t)kh * SEQ + s) * HD;
        }
        float4 x = *(const float4*)(base + d);
        float ss = x.x * x.x + x.y * x.y + x.z * x.z + x.w * x.w;
        #pragma unroll
        for (int o = 16; o > 0; o >>= 1) ss += __shfl_xor_sync(0xffffffffu, ss, o);
        float r = rsqrtf(ss * (1.0f / 128.0f) + 1e-6f);

        float4 wv = *(const float4*)(w + d);
        float4 xn;
        xn.x = x.x * r * wv.x; xn.y = x.y * r * wv.y;
        xn.z = x.z * r * wv.z; xn.w = x.w * r * wv.w;

        float4 ot;
        ot.x = __shfl_xor_sync(0xffffffffu, xn.x, 16);
        ot.y = __shfl_xor_sync(0xffffffffu, xn.y, 16);
        ot.z = __shfl_xor_sync(0xffffffffu, xn.z, 16);
        ot.w = __shfl_xor_sync(0xffffffffu, xn.w, 16);
        float sgn = (d < 64) ? -1.0f : 1.0f;

        float4 c = *(const float4*)(cosb + (size_t)s * HD + d);
        float4 si = *(const float4*)(sinb + (size_t)s * HD + d);
        out.x = xn.x * c.x + sgn * ot.x * si.x;
        out.y = xn.y * c.y + sgn * ot.y * si.y;
        out.z = xn.z * c.z + sgn * ot.z * si.z;
        out.w = xn.w * c.w + sgn * ot.w * si.w;
        if (h < NQH) {
            const float sc = 0.12751743f;   // (1/sqrt(128)) * log2(e)
            out.x *= sc; out.y *= sc; out.z *= sc; out.w *= sc;
        }
    } else {
        int vh = h - 40;
        const float* base = g_qkv + (size_t)s * QKVD + QD + KVD + vh * HD;
        out = *(const float4*)(base + d);
        dsingle = g_vh + ((size_t)vh * SEQ + s) * HD;
    }

    *(__half2*)(dsingle + d)     = __floats2half2_rn(out.x, out.y);
    *(__half2*)(dsingle + d + 2) = __floats2half2_rn(out.z, out.w);
}

// ---------------------------------------------------------------------------
// Tensor-core flash attention, causal, GQA. log2-domain softmax (ex2.f16x2).
// CTA = (head, 128-row q tile), 8 warps. 3-stage KV pipeline.
// ---------------------------------------------------------------------------
#define ASTR 136                   // halves per smem row
#define AKV  (64 * ASTR)           // halves per KV matrix
#define AQ   (128 * ASTR)          // halves per Q matrix
#define ATTN_SMEM ((AQ + 6 * AKV) * 2)   // 139264 B

__global__ __launch_bounds__(256, 1)
void flash_mma_kernel() {
    extern __shared__ __half asm_smem[];
    const uint32_t sb = smem_u32(asm_smem);
    const uint32_t sQ = sb;
    const uint32_t kvb = sQ + AQ * 2;
    const uint32_t sK[3] = { kvb, kvb + 2 * AKV * 2, kvb + 4 * AKV * 2 };
    const uint32_t sV[3] = { kvb + AKV * 2, kvb + 3 * AKV * 2, kvb + 5 * AKV * 2 };

    const int h  = blockIdx.x;
    const int qt = gridDim.y - 1 - blockIdx.y;   // longest tiles first
    const int q0 = qt * 128;
    const int kh = h >> 2;
    const int tid = threadIdx.x;
    const int warp = tid >> 5;
    const int lane = tid & 31;
    const int gid = lane >> 2;
    const int tig = lane & 3;

    const __half* bkh = g_kh + (size_t)kh * SEQ * HD;
    const __half* bvh = g_vh + (size_t)kh * SEQ * HD;

    auto load_kv = [&](int it, int buf) {
        const __half* pk = bkh + (size_t)(it * 64) * HD;
        const __half* pv = bvh + (size_t)(it * 64) * HD;
        #pragma unroll
        for (int i = 0; i < 4; i++) {
            int ch = tid + i * 256;
            int row = ch >> 4, c = ch & 15;
            uint32_t off = (uint32_t)(row * ASTR) * 2 + c * 16;
            size_t goff = (size_t)row * HD + c * 8;
            cpa16(sK[buf] + off, pk + goff);
            cpa16(sV[buf] + off, pv + goff);
        }
    };

    const int nit = 2 * qt + 1;              // KV tiles 0..nit

    {
        const __half* gq = g_qh + ((size_t)h * SEQ + q0) * HD;
        #pragma unroll
        for (int i = 0; i < 8; i++) {
            int ch = tid + i * 256;
            int row = ch >> 4, c = ch & 15;
            uint32_t off = (uint32_t)(row * ASTR) * 2 + c * 16;
            cpa16(sQ + off, gq + (size_t)row * HD + c * 8);
        }
        load_kv(0, 0);
        cpa_commit();
        load_kv(1, 1);
        cpa_commit();
    }

    float oacc[16][4];
    #pragma unroll
    for (int j = 0; j < 16; j++)
        #pragma unroll
        for (int t = 0; t < 4; t++) oacc[j][t] = 0.0f;
    float mrow[2] = {-1e30f, -1e30f};
    float lrow[2] = {0.0f, 0.0f};

    const uint32_t qoff_row = (uint32_t)((warp * 16 + (lane & 15)) * ASTR) * 2;
    const uint32_t qoff_col = (uint32_t)((lane >> 4) * 8) * 2;
    const uint32_t koff_rowbase = (uint32_t)((lane & 7) * ASTR) * 2;
    const uint32_t koff_col = (uint32_t)(((lane >> 3) & 3) * 8) * 2;
    const uint32_t voff_rowbase = (uint32_t)(((lane & 7) + 8 * ((lane >> 3) & 1)) * ASTR) * 2;
    const uint32_t voff_col = (uint32_t)((lane >> 4) * 8) * 2;

    for (int it = 0; it <= nit; it++) {
        const int cur = it % 3;
        if (it == nit) cpa_wait0(); else cpa_wait1();
        __syncthreads();
        if (it + 1 < nit) {
            load_kv(it + 2, (it + 2) % 3);
            cpa_commit();
        }
        const bool active = !(it == nit && warp < 4);
        if (active) {
            const uint32_t sKc = sK[cur];
            const uint32_t sVc = sV[cur];

            float sacc[8][4];
            #pragma unroll
            for (int j = 0; j < 8; j++)
                #pragma unroll
                for (int t = 0; t < 4; t++) sacc[j][t] = 0.0f;

            #pragma unroll
            for (int ks2 = 0; ks2 < 4; ks2++) {
                uint32_t qf[2][4];
                #pragma unroll
                for (int e = 0; e < 2; e++) {
                    uint32_t off = qoff_row + ((uint32_t)((ks2 * 2 + e) * 16) * 2 + qoff_col);
                    ldm_x4(qf[e], sQ + off);
                }
                #pragma unroll
                for (int jn2 = 0; jn2 < 4; jn2++) {
                    const int jA = jn2 * 2, jB = jn2 * 2 + 1;
                    const uint32_t kcom = koff_rowbase + (uint32_t)(ks2 * 32) * 2 + koff_col;
                    uint32_t offA = (uint32_t)(jA * 8 * ASTR) * 2 + kcom;
                    uint32_t offB = (uint32_t)(jB * 8 * ASTR) * 2 + kcom;
                    uint32_t khA[4], khB[4];
                    ldm_x4(khA, sKc + offA); ldm_x4(khB, sKc + offB);
                    mma_f16(sacc[jA], qf[0], khA);     mma_f16(sacc[jB], qf[0], khB);
                    mma_f16(sacc[jA], qf[1], khA + 2); mma_f16(sacc[jB], qf[1], khB + 2);
                }
            }

            if (it >= 2 * qt) {
                int qg0 = q0 + warp * 16 + gid;
                #pragma unroll
                for (int jn = 0; jn < 8; jn++) {
                    int kg = it * 64 + jn * 8 + tig * 2;
                    if (kg > qg0)     sacc[jn][0] = -1e30f;
                    if (kg + 1 > qg0) sacc[jn][1] = -1e30f;
                    if (kg > qg0 + 8)     sacc[jn][2] = -1e30f;
                    if (kg + 1 > qg0 + 8) sacc[jn][3] = -1e30f;
                }
            }

            float mn0 = mrow[0], mn1 = mrow[1];
            #pragma unroll
            for (int jn = 0; jn < 8; jn++) {
                mn0 = fmaxf(mn0, fmaxf(sacc[jn][0], sacc[jn][1]));
                mn1 = fmaxf(mn1, fmaxf(sacc[jn][2], sacc[jn][3]));
            }
            mn0 = fmaxf(mn0, __shfl_xor_sync(0xffffffffu, mn0, 1));
            mn0 = fmaxf(mn0, __shfl_xor_sync(0xffffffffu, mn0, 2));
            mn1 = fmaxf(mn1, __shfl_xor_sync(0xffffffffu, mn1, 1));
            mn1 = fmaxf(mn1, __shfl_xor_sync(0xffffffffu, mn1, 2));
            float al0 = exp2f(mrow[0] - mn0);
            float al1 = exp2f(mrow[1] - mn1);
            mrow[0] = mn0; mrow[1] = mn1;
            lrow[0] *= al0; lrow[1] *= al1;

            uint32_t ph[8][2];
            float lacc0 = 0.0f, lacc1 = 0.0f;
            #pragma unroll
            for (int jn = 0; jn < 8; jn++) {
                uint32_t p0 = ex2_h2(sacc[jn][0] - mn0, sacc[jn][1] - mn0);
                uint32_t p1 = ex2_h2(sacc[jn][2] - mn1, sacc[jn][3] - mn1);
                ph[jn][0] = p0;
                ph[jn][1] = p1;
                float2 f0 = __half22float2(*(__half2*)&p0);
                float2 f1 = __half22float2(*(__half2*)&p1);
                lacc0 += f0.x + f0.y;
                lacc1 += f1.x + f1.y;
            }
            lrow[0] += lacc0;
            lrow[1] += lacc1;

            #pragma unroll
            for (int jd = 0; jd < 16; jd++) {
                oacc[jd][0] *= al0; oacc[jd][1] *= al0;
                oacc[jd][2] *= al1; oacc[jd][3] *= al1;
            }

            #pragma unroll
            for (int kks = 0; kks < 4; kks++) {
                uint32_t aPh[4] = {ph[2 * kks][0], ph[2 * kks][1],
                                   ph[2 * kks + 1][0], ph[2 * kks + 1][1]};
                #pragma unroll
                for (int jd2 = 0; jd2 < 8; jd2++) {
                    uint32_t off = (uint32_t)(kks * 16 * ASTR) * 2 + voff_rowbase +
                                   (uint32_t)(jd2 * 16) * 2 + voff_col;
                    uint32_t vh4[4];
                    ldm_x4_t(vh4, sVc + off);
                    mma_f16(oacc[jd2 * 2], aPh, vh4);
                    mma_f16(oacc[jd2 * 2 + 1], aPh, vh4 + 2);
                }
            }
        }
    }

    lrow[0] += __shfl_xor_sync(0xffffffffu, lrow[0], 1);
    lrow[0] += __shfl_xor_sync(0xffffffffu, lrow[0], 2);
    lrow[1] += __shfl_xor_sync(0xffffffffu, lrow[1], 1);
    lrow[1] += __shfl_xor_sync(0xffffffffu, lrow[1], 2);
    float inv0 = 1.0f / lrow[0];
    float inv1 = 1.0f / lrow[1];

    int row0 = q0 + warp * 16 + gid;
    #pragma unroll
    for (int jd = 0; jd < 16; jd++) {
        int col = h * HD + jd * 8 + tig * 2;
        __half2 h0 = __floats2half2_rn(oacc[jd][0] * inv0, oacc[jd][1] * inv0);
        __half2 h1 = __floats2half2_rn(oacc[jd][2] * inv1, oacc[jd][3] * inv1);
        *(__half2*)(g_ao_h + (size_t)row0 * QD + col)       = h0;
        *(__half2*)(g_ao_h + (size_t)(row0 + 8) * QD + col) = h1;
    }
}

// ---------------------------------------------------------------------------
// launch
// ---------------------------------------------------------------------------
extern "C" void kernel_launch(void* const* d_in, const int* in_sizes, int n_in,
                              void* d_out, int out_size) {
    const float* hidden = (const float*)d_in[0];
    const float* cosb   = (const float*)d_in[1];
    const float* sinb   = (const float*)d_in[2];
    const float* Wq     = (const float*)d_in[3];
    const float* Wk     = (const float*)d_in[4];
    const float* Wv     = (const float*)d_in[5];
    const float* Wo     = (const float*)d_in[6];
    const float* qw     = (const float*)d_in[7];
    const float* kw     = (const float*)d_in[8];
    float* out = (float*)d_out;

    float *qkv_ptr = nullptr, *part_ptr = nullptr;
    __half *hid_h, *wqkv_h, *wo_h, *ao_h;
    cudaGetSymbolAddress((void**)&qkv_ptr, g_qkv);
    cudaGetSymbolAddress((void**)&part_ptr, g_part);
    cudaGetSymbolAddress((void**)&hid_h, g_hid_h);
    cudaGetSymbolAddress((void**)&wqkv_h, g_wqkv_h);
    cudaGetSymbolAddress((void**)&wo_h, g_wo_h);
    cudaGetSymbolAddress((void**)&ao_h, g_ao_h);

    cudaFuncSetAttribute(gemm_mma, cudaFuncAttributeMaxDynamicSharedMemorySize, GEMM_SMEM);
    cudaFuncSetAttribute(flash_mma_kernel, cudaFuncAttributeMaxDynamicSharedMemorySize, ATTN_SMEM);

    // fused conversions to fp16 (one launch)
    {
        size_t total = (size_t)SEQ * HID + (size_t)QD * HID + 2 * (size_t)KVD * HID +
                       (size_t)HID * QD;
        int nthreads4 = (int)(total / 4);
        cvt_all<<<(nthreads4 + 255) / 256, 256>>>(hidden, Wq, Wk, Wv, Wo);
    }

    // fused QKV projection: g_qkv[2048, 6144] = hidden @ [Wq|Wk|Wv]^T
    gemm_mma<<<dim3(QKVD / 128, SEQ / 128), 128, GEMM_SMEM>>>(
        hid_h, wqkv_h, qkv_ptr, HID, 0, HID, QKVD);

    // RMSNorm + RoPE + fp16 conversion into [h][s][d] buffers
    {
        int nwarps = SEQ * 48;
        int nblocks = (nwarps * 32 + 255) / 256;
        rms_rope_kernel<<<nblocks, 256>>>(cosb, sinb, qw, kw);
    }

    // tensor-core causal GQA flash attention -> g_ao_h
    flash_mma_kernel<<<dim3(NQH, SEQ / 128), 256, ATTN_SMEM>>>();

    // output projection, split-K=2: out = O[:, :2048] @ Wo1^T; part = O[:, 2048:] @ Wo2^T
    gemm_mma<<<dim3(HID / 128, SEQ / 128), 128, GEMM_SMEM>>>(
        ao_h, wo_h, out, QD, 0, QD / 2, HID);
    gemm_mma<<<dim3(HID / 128, SEQ / 128), 128, GEMM_SMEM>>>(
        ao_h, wo_h, part_ptr, QD, QD / 2, QD / 2, HID);
    {
        int n = SEQ * HID;
        add_kernel<<<(n / 4 + 255) / 256, 256>>>(out, part_ptr, n);
    }
}

// round 15
// speedup vs baseline: 1.1586x; 1.1586x over previous
#include <cuda_runtime.h>
#include <cuda_fp16.h>
#include <cstdint>
#include <cstdio>

#define SEQ   2048
#define HID   2560
#define QD    4096      // 32 heads * 128
#define KVD   1024      // 8 heads * 128
#define QKVD  6144      // QD + 2*KVD
#define HD    128
#define NQH   32
#define NKVH  8

// ---------------------------------------------------------------------------
// Scratch (device globals; no allocation allowed)
// ---------------------------------------------------------------------------
__device__ float g_qkv[(size_t)SEQ * QKVD];   // [s, 6144]: Q | K | V (fp32)

// fp16 operand buffers
__device__ __half g_hid_h[(size_t)SEQ * HID];     // hidden (A of QKV gemm)
__device__ __half g_wqkv_h[(size_t)QKVD * HID];   // Wq|Wk|Wv stacked (B)
__device__ __half g_wo_h[(size_t)HID * QD];       // Wo (B)
__device__ __half g_ao_h[(size_t)SEQ * QD];       // attn out (A of Wo gemm)

// attention operands, [head][seq][128]
__device__ __half g_qh[(size_t)NQH * SEQ * HD];   // Q (scale*log2e folded)
__device__ __half g_kh[(size_t)NKVH * SEQ * HD];  // K
__device__ __half g_vh[(size_t)NKVH * SEQ * HD];  // V

// ---------------------------------------------------------------------------
// PTX helpers
// ---------------------------------------------------------------------------
__device__ __forceinline__ uint32_t smem_u32(const void* p) {
    uint32_t a;
    asm("{ .reg .u64 t; cvta.to.shared.u64 t, %1; cvt.u32.u64 %0, t; }" : "=r"(a) : "l"(p));
    return a;
}
__device__ __forceinline__ void cpa16(uint32_t s, const void* g) {
    asm volatile("cp.async.cg.shared.global [%0], [%1], 16;" :: "r"(s), "l"(g));
}
__device__ __forceinline__ void cpa_commit() {
    asm volatile("cp.async.commit_group;" ::: "memory");
}
__device__ __forceinline__ void cpa_wait1() {
    asm volatile("cp.async.wait_group 1;" ::: "memory");
}
__device__ __forceinline__ void cpa_wait0() {
    asm volatile("cp.async.wait_group 0;" ::: "memory");
}
__device__ __forceinline__ void ldm_x4(uint32_t* r, uint32_t addr) {
    asm volatile("ldmatrix.sync.aligned.m8n8.x4.shared.b16 {%0,%1,%2,%3}, [%4];"
                 : "=r"(r[0]), "=r"(r[1]), "=r"(r[2]), "=r"(r[3]) : "r"(addr));
}
__device__ __forceinline__ void ldm_x4_t(uint32_t* r, uint32_t addr) {
    asm volatile("ldmatrix.sync.aligned.m8n8.x4.trans.shared.b16 {%0,%1,%2,%3}, [%4];"
                 : "=r"(r[0]), "=r"(r[1]), "=r"(r[2]), "=r"(r[3]) : "r"(addr));
}
__device__ __forceinline__ void mma_f16(float* c, const uint32_t* a, const uint32_t* b) {
    asm volatile(
        "mma.sync.aligned.m16n8k16.row.col.f32.f16.f16.f32 "
        "{%0,%1,%2,%3}, {%4,%5,%6,%7}, {%8,%9}, {%0,%1,%2,%3};"
        : "+f"(c[0]), "+f"(c[1]), "+f"(c[2]), "+f"(c[3])
        : "r"(a[0]), "r"(a[1]), "r"(a[2]), "r"(a[3]), "r"(b[0]), "r"(b[1]));
}
__device__ __forceinline__ uint32_t ex2_h2(float a, float b) {
    __half2 t = __floats2half2_rn(a, b);
    uint32_t in = *(uint32_t*)&t, out;
    asm("ex2.approx.f16x2 %0, %1;" : "=r"(out) : "r"(in));
    return out;
}

// ---------------------------------------------------------------------------
// fused fp32 -> fp16 conversion over all 5 input regions (one launch)
// ---------------------------------------------------------------------------
__global__ __launch_bounds__(256)
void cvt_all(const float* __restrict__ hid, const float* __restrict__ wq,
             const float* __restrict__ wk, const float* __restrict__ wv,
             const float* __restrict__ wo) {
    size_t i = ((size_t)blockIdx.x * blockDim.x + threadIdx.x) * 4;
    const size_t n0 = (size_t)SEQ * HID;
    const size_t n1 = (size_t)QD * HID;
    const size_t n2 = (size_t)KVD * HID;
    const size_t n4 = (size_t)HID * QD;

    const float* src;
    __half* dst;
    if (i < n0)                { src = hid; dst = g_hid_h + i; }
    else if ((i -= n0) < n1)   { src = wq;  dst = g_wqkv_h + i; }
    else if ((i -= n1) < n2)   { src = wk;  dst = g_wqkv_h + n1 + i; }
    else if ((i -= n2) < n2)   { src = wv;  dst = g_wqkv_h + n1 + n2 + i; }
    else if ((i -= n2) < n4)   { src = wo;  dst = g_wo_h + i; }
    else return;

    float4 x = *(const float4*)(src + i);
    *(__half2*)(dst)     = __floats2half2_rn(x.x, x.y);
    *(__half2*)(dst + 2) = __floats2half2_rn(x.z, x.w);
}

// ---------------------------------------------------------------------------
// mma.sync fp16 GEMM (NT): C[m,n] = sum_k A[m,k]*B[n,k], fp32 accum.
// CTA 128x128, BK=64, 8 warps (4x2), warp tile 32x64.
// 3-stage cp.async ring, ONE barrier per chunk, 2-chunk prefetch depth.
// (round-13 proven configuration)
// ---------------------------------------------------------------------------
#define BK 64
#define LDS_STR 72                    // 64 halves + 8 pad (conflict-free)
#define TILE_H (128 * LDS_STR)
#define STAGE_H (2 * TILE_H)          // A | B
#define GEMM_SMEM (3 * STAGE_H * 2)   // 110592 B

__global__ __launch_bounds__(256, 2)
void gemm_mma(const __half* __restrict__ Ah, const __half* __restrict__ Bh,
              float* __restrict__ C, int K, int ldc) {
    extern __shared__ __half smem[];
    const uint32_t sbase = smem_u32(smem);

    const int tid  = threadIdx.x;
    const int warp = tid >> 5;
    const int lane = tid & 31;
    const int wm   = warp & 3;
    const int wn   = warp >> 2;
    const int bx = blockIdx.x, by = blockIdx.y;

    const __half* gA = Ah + (size_t)(by * 128) * K;
    const __half* gB = Bh + (size_t)(bx * 128) * K;

    float acc[2][8][4];
    #pragma unroll
    for (int i = 0; i < 2; i++)
        #pragma unroll
        for (int j = 0; j < 8; j++)
            #pragma unroll
            for (int t = 0; t < 4; t++) acc[i][j][t] = 0.0f;

    const int nchunk = K / BK;
    const int r0 = tid >> 2;
    const int ch0 = (tid & 3) * 8;

    auto load_stage = [&](int c, int s) {
        const size_t koff = (size_t)c * BK;
        uint32_t dst = sbase + (uint32_t)(s * STAGE_H) * 2;
        {
            const __half* a0 = gA + (size_t)r0 * K + koff;
            const __half* a1 = gA + (size_t)(r0 + 64) * K + koff;
            cpa16(dst + (r0 * LDS_STR + ch0) * 2,              a0 + ch0);
            cpa16(dst + (r0 * LDS_STR + ch0 + 32) * 2,         a0 + ch0 + 32);
            cpa16(dst + ((r0 + 64) * LDS_STR + ch0) * 2,       a1 + ch0);
            cpa16(dst + ((r0 + 64) * LDS_STR + ch0 + 32) * 2,  a1 + ch0 + 32);
        }
        {
            uint32_t d = dst + (uint32_t)TILE_H * 2;
            const __half* b0 = gB + (size_t)r0 * K + koff;
            const __half* b1 = gB + (size_t)(r0 + 64) * K + koff;
            cpa16(d + (r0 * LDS_STR + ch0) * 2,              b0 + ch0);
            cpa16(d + (r0 * LDS_STR + ch0 + 32) * 2,         b0 + ch0 + 32);
            cpa16(d + ((r0 + 64) * LDS_STR + ch0) * 2,       b1 + ch0);
            cpa16(d + ((r0 + 64) * LDS_STR + ch0 + 32) * 2,  b1 + ch0 + 32);
        }
    };

    const int a_row = (lane & 7) + ((lane >> 3) & 1) * 8;
    const int a_kof = (lane >> 4) * 8;
    const int b_mat = lane >> 3;
    const int b_row = lane & 7;
    const int b_kof = (b_mat & 1) * 8;
    const int b_jof = (b_mat >> 1);

    load_stage(0, 0);
    cpa_commit();
    load_stage(1, 1);
    cpa_commit();

    int stage = 0;
    for (int c = 0; c < nchunk; c++) {
        if (c == nchunk - 1) cpa_wait0(); else cpa_wait1();
        __syncthreads();
        if (c + 2 < nchunk) {
            int s2 = stage + 2; if (s2 >= 3) s2 -= 3;
            load_stage(c + 2, s2);
            cpa_commit();
        }

        const uint32_t st = sbase + (uint32_t)(stage * STAGE_H) * 2;
        const uint32_t sA = st;
        const uint32_t sB = st + (uint32_t)TILE_H * 2;

        #pragma unroll
        for (int ks = 0; ks < 4; ks++) {
            uint32_t ah[2][4];
            #pragma unroll
            for (int i = 0; i < 2; i++) {
                int m_local = wm * 32 + i * 16 + a_row;
                uint32_t off = (uint32_t)(m_local * LDS_STR + ks * 16 + a_kof) * 2;
                ldm_x4(ah[i], sA + off);
            }
            #pragma unroll
            for (int jp = 0; jp < 4; jp++) {
                int n_local = wn * 64 + (jp * 2 + b_jof) * 8 + b_row;
                uint32_t off = (uint32_t)(n_local * LDS_STR + ks * 16 + b_kof) * 2;
                uint32_t rh[4];
                ldm_x4(rh, sB + off);
                const int j0 = jp * 2, j1 = jp * 2 + 1;
                mma_f16(acc[0][j0], ah[0], rh);   mma_f16(acc[0][j1], ah[0], rh + 2);
                mma_f16(acc[1][j0], ah[1], rh);   mma_f16(acc[1][j1], ah[1], rh + 2);
            }
        }
        if (++stage == 3) stage = 0;
    }

    const int gid = lane >> 2;
    const int tgc = (lane & 3) * 2;
    #pragma unroll
    for (int i = 0; i < 2; i++) {
        int row = by * 128 + wm * 32 + i * 16 + gid;
        #pragma unroll
        for (int j = 0; j < 8; j++) {
            int col = bx * 128 + wn * 64 + j * 8 + tgc;
            float2 v0 = {acc[i][j][0], acc[i][j][1]};
            float2 v1 = {acc[i][j][2], acc[i][j][3]};
            *(float2*)(C + (size_t)row * ldc + col)       = v0;
            *(float2*)(C + (size_t)(row + 8) * ldc + col) = v1;
        }
    }
}

// ---------------------------------------------------------------------------
// gemm64: same structure, CTA tile 64(M)x128(N), 8 warps (2x4), warp 32x32.
// Smaller tiles kill the Wo wave-quantization tail (640 CTAs of half length).
// ---------------------------------------------------------------------------
#define A64_H (64 * LDS_STR)              // 4608 halves
#define STAGE64_H (A64_H + TILE_H)        // A(64 rows) | B(128 rows)
#define GEMM64_SMEM (3 * STAGE64_H * 2)   // 82944 B

__global__ __launch_bounds__(256, 2)
void gemm64_mma(const __half* __restrict__ Ah, const __half* __restrict__ Bh,
                float* __restrict__ C, int K, int ldc) {
    extern __shared__ __half smem[];
    const uint32_t sbase = smem_u32(smem);

    const int tid  = threadIdx.x;
    const int warp = tid >> 5;
    const int lane = tid & 31;
    const int wm   = warp & 1;        // rows wm*32
    const int wn   = warp >> 1;       // cols wn*32
    const int bx = blockIdx.x, by = blockIdx.y;

    const __half* gA = Ah + (size_t)(by * 64) * K;
    const __half* gB = Bh + (size_t)(bx * 128) * K;

    float acc[2][4][4];
    #pragma unroll
    for (int i = 0; i < 2; i++)
        #pragma unroll
        for (int j = 0; j < 4; j++)
            #pragma unroll
            for (int t = 0; t < 4; t++) acc[i][j][t] = 0.0f;

    const int nchunk = K / BK;
    // A: 64 rows, 4 threads/row, 16 halves each
    const int ra = tid >> 2;
    const int ca = (tid & 3) * 16;
    // B: 128 rows, 2 threads/row, 32 halves each
    const int rb = tid >> 1;
    const int cb = (tid & 1) * 32;

    auto load_stage = [&](int c, int s) {
        const size_t koff = (size_t)c * BK;
        uint32_t dst = sbase + (uint32_t)(s * STAGE64_H) * 2;
        {
            const __half* a0 = gA + (size_t)ra * K + koff + ca;
            uint32_t d = dst + (uint32_t)(ra * LDS_STR + ca) * 2;
            cpa16(d,      a0);
            cpa16(d + 16, a0 + 8);
        }
        {
            const __half* b0 = gB + (size_t)rb * K + koff + cb;
            uint32_t d = dst + (uint32_t)A64_H * 2 + (uint32_t)(rb * LDS_STR + cb) * 2;
            cpa16(d,      b0);
            cpa16(d + 16, b0 + 8);
            cpa16(d + 32, b0 + 16);
            cpa16(d + 48, b0 + 24);
        }
    };

    const int a_row = (lane & 7) + ((lane >> 3) & 1) * 8;
    const int a_kof = (lane >> 4) * 8;
    const int b_mat = lane >> 3;
    const int b_row = lane & 7;
    const int b_kof = (b_mat & 1) * 8;
    const int b_jof = (b_mat >> 1);

    load_stage(0, 0);
    cpa_commit();
    load_stage(1, 1);
    cpa_commit();

    int stage = 0;
    for (int c = 0; c < nchunk; c++) {
        if (c == nchunk - 1) cpa_wait0(); else cpa_wait1();
        __syncthreads();
        if (c + 2 < nchunk) {
            int s2 = stage + 2; if (s2 >= 3) s2 -= 3;
            load_stage(c + 2, s2);
            cpa_commit();
        }

        const uint32_t st = sbase + (uint32_t)(stage * STAGE64_H) * 2;
        const uint32_t sA = st;
        const uint32_t sB = st + (uint32_t)A64_H * 2;

        #pragma unroll
        for (int ks = 0; ks < 4; ks++) {
            uint32_t ah[2][4];
            #pragma unroll
            for (int i = 0; i < 2; i++) {
                int m_local = wm * 32 + i * 16 + a_row;
                uint32_t off = (uint32_t)(m_local * LDS_STR + ks * 16 + a_kof) * 2;
                ldm_x4(ah[i], sA + off);
            }
            #pragma unroll
            for (int jp = 0; jp < 2; jp++) {
                int n_local = wn * 32 + (jp * 2 + b_jof) * 8 + b_row;
                uint32_t off = (uint32_t)(n_local * LDS_STR + ks * 16 + b_kof) * 2;
                uint32_t rh[4];
                ldm_x4(rh, sB + off);
                const int j0 = jp * 2, j1 = jp * 2 + 1;
                mma_f16(acc[0][j0], ah[0], rh);   mma_f16(acc[0][j1], ah[0], rh + 2);
                mma_f16(acc[1][j0], ah[1], rh);   mma_f16(acc[1][j1], ah[1], rh + 2);
            }
        }
        if (++stage == 3) stage = 0;
    }

    const int gid = lane >> 2;
    const int tgc = (lane & 3) * 2;
    #pragma unroll
    for (int i = 0; i < 2; i++) {
        int row = by * 64 + wm * 32 + i * 16 + gid;
        #pragma unroll
        for (int j = 0; j < 4; j++) {
            int col = bx * 128 + wn * 32 + j * 8 + tgc;
            float2 v0 = {acc[i][j][0], acc[i][j][1]};
            float2 v1 = {acc[i][j][2], acc[i][j][3]};
            *(float2*)(C + (size_t)row * ldc + col)       = v0;
            *(float2*)(C + (size_t)(row + 8) * ldc + col) = v1;
        }
    }
}

// ---------------------------------------------------------------------------
// RMSNorm + RoPE, fp32 g_qkv -> fp16 buffers, [h][s][d] layout.
// ---------------------------------------------------------------------------
__global__ __launch_bounds__(256)
void rms_rope_kernel(const float* __restrict__ cosb, const float* __restrict__ sinb,
                     const float* __restrict__ qw, const float* __restrict__ kw) {
    int gw = (blockIdx.x * blockDim.x + threadIdx.x) >> 5;
    int lane = threadIdx.x & 31;
    if (gw >= SEQ * 48) return;
    int s = gw / 48;
    int h = gw % 48;
    int d = lane * 4;

    float4 out;
    __half* dsingle;

    if (h < 40) {
        const float* base;
        const float* w;
        if (h < NQH) {
            base = g_qkv + (size_t)s * QKVD + h * HD;
            w = qw;
            dsingle = g_qh + ((size_t)h * SEQ + s) * HD;
        } else {
            int kh = h - NQH;
            base = g_qkv + (size_t)s * QKVD + QD + kh * HD;
            w = kw;
            dsingle = g_kh + ((size_t)kh * SEQ + s) * HD;
        }
        float4 x = *(const float4*)(base + d);
        float ss = x.x * x.x + x.y * x.y + x.z * x.z + x.w * x.w;
        #pragma unroll
        for (int o = 16; o > 0; o >>= 1) ss += __shfl_xor_sync(0xffffffffu, ss, o);
        float r = rsqrtf(ss * (1.0f / 128.0f) + 1e-6f);

        float4 wv = *(const float4*)(w + d);
        float4 xn;
        xn.x = x.x * r * wv.x; xn.y = x.y * r * wv.y;
        xn.z = x.z * r * wv.z; xn.w = x.w * r * wv.w;

        float4 ot;
        ot.x = __shfl_xor_sync(0xffffffffu, xn.x, 16);
        ot.y = __shfl_xor_sync(0xffffffffu, xn.y, 16);
        ot.z = __shfl_xor_sync(0xffffffffu, xn.z, 16);
        ot.w = __shfl_xor_sync(0xffffffffu, xn.w, 16);
        float sgn = (d < 64) ? -1.0f : 1.0f;

        float4 c = *(const float4*)(cosb + (size_t)s * HD + d);
        float4 si = *(const float4*)(sinb + (size_t)s * HD + d);
        out.x = xn.x * c.x + sgn * ot.x * si.x;
        out.y = xn.y * c.y + sgn * ot.y * si.y;
        out.z = xn.z * c.z + sgn * ot.z * si.z;
        out.w = xn.w * c.w + sgn * ot.w * si.w;
        if (h < NQH) {
            const float sc = 0.12751743f;   // (1/sqrt(128)) * log2(e)
            out.x *= sc; out.y *= sc; out.z *= sc; out.w *= sc;
        }
    } else {
        int vh = h - 40;
        const float* base = g_qkv + (size_t)s * QKVD + QD + KVD + vh * HD;
        out = *(const float4*)(base + d);
        dsingle = g_vh + ((size_t)vh * SEQ + s) * HD;
    }

    *(__half2*)(dsingle + d)     = __floats2half2_rn(out.x, out.y);
    *(__half2*)(dsingle + d + 2) = __floats2half2_rn(out.z, out.w);
}

// ---------------------------------------------------------------------------
// Tensor-core flash attention, causal, GQA. log2-domain softmax (ex2.f16x2).
// CTA = (head, 128-row q tile), 8 warps. 3-stage KV pipeline.
// ---------------------------------------------------------------------------
#define ASTR 136                   // halves per smem row
#define AKV  (64 * ASTR)           // halves per KV matrix
#define AQ   (128 * ASTR)          // halves per Q matrix
#define ATTN_SMEM ((AQ + 6 * AKV) * 2)   // 139264 B

__global__ __launch_bounds__(256, 1)
void flash_mma_kernel() {
    extern __shared__ __half asm_smem[];
    const uint32_t sb = smem_u32(asm_smem);
    const uint32_t sQ = sb;
    const uint32_t kvb = sQ + AQ * 2;
    const uint32_t sK[3] = { kvb, kvb + 2 * AKV * 2, kvb + 4 * AKV * 2 };
    const uint32_t sV[3] = { kvb + AKV * 2, kvb + 3 * AKV * 2, kvb + 5 * AKV * 2 };

    const int h  = blockIdx.x;
    const int qt = gridDim.y - 1 - blockIdx.y;   // longest tiles first
    const int q0 = qt * 128;
    const int kh = h >> 2;
    const int tid = threadIdx.x;
    const int warp = tid >> 5;
    const int lane = tid & 31;
    const int gid = lane >> 2;
    const int tig = lane & 3;

    const __half* bkh = g_kh + (size_t)kh * SEQ * HD;
    const __half* bvh = g_vh + (size_t)kh * SEQ * HD;

    auto load_kv = [&](int it, int buf) {
        const __half* pk = bkh + (size_t)(it * 64) * HD;
        const __half* pv = bvh + (size_t)(it * 64) * HD;
        #pragma unroll
        for (int i = 0; i < 4; i++) {
            int ch = tid + i * 256;
            int row = ch >> 4, c = ch & 15;
            uint32_t off = (uint32_t)(row * ASTR) * 2 + c * 16;
            size_t goff = (size_t)row * HD + c * 8;
            cpa16(sK[buf] + off, pk + goff);
            cpa16(sV[buf] + off, pv + goff);
        }
    };

    const int nit = 2 * qt + 1;              // KV tiles 0..nit

    {
        const __half* gq = g_qh + ((size_t)h * SEQ + q0) * HD;
        #pragma unroll
        for (int i = 0; i < 8; i++) {
            int ch = tid + i * 256;
            int row = ch >> 4, c = ch & 15;
            uint32_t off = (uint32_t)(row * ASTR) * 2 + c * 16;
            cpa16(sQ + off, gq + (size_t)row * HD + c * 8);
        }
        load_kv(0, 0);
        cpa_commit();
        load_kv(1, 1);
        cpa_commit();
    }

    float oacc[16][4];
    #pragma unroll
    for (int j = 0; j < 16; j++)
        #pragma unroll
        for (int t = 0; t < 4; t++) oacc[j][t] = 0.0f;
    float mrow[2] = {-1e30f, -1e30f};
    float lrow[2] = {0.0f, 0.0f};

    const uint32_t qoff_row = (uint32_t)((warp * 16 + (lane & 15)) * ASTR) * 2;
    const uint32_t qoff_col = (uint32_t)((lane >> 4) * 8) * 2;
    const uint32_t koff_rowbase = (uint32_t)((lane & 7) * ASTR) * 2;
    const uint32_t koff_col = (uint32_t)(((lane >> 3) & 3) * 8) * 2;
    const uint32_t voff_rowbase = (uint32_t)(((lane & 7) + 8 * ((lane >> 3) & 1)) * ASTR) * 2;
    const uint32_t voff_col = (uint32_t)((lane >> 4) * 8) * 2;

    for (int it = 0; it <= nit; it++) {
        const int cur = it % 3;
        if (it == nit) cpa_wait0(); else cpa_wait1();
        __syncthreads();
        if (it + 1 < nit) {
            load_kv(it + 2, (it + 2) % 3);
            cpa_commit();
        }
        const bool active = !(it == nit && warp < 4);
        if (active) {
            const uint32_t sKc = sK[cur];
            const uint32_t sVc = sV[cur];

            float sacc[8][4];
            #pragma unroll
            for (int j = 0; j < 8; j++)
                #pragma unroll
                for (int t = 0; t < 4; t++) sacc[j][t] = 0.0f;

            #pragma unroll
            for (int ks2 = 0; ks2 < 4; ks2++) {
                uint32_t qf[2][4];
                #pragma unroll
                for (int e = 0; e < 2; e++) {
                    uint32_t off = qoff_row + ((uint32_t)((ks2 * 2 + e) * 16) * 2 + qoff_col);
                    ldm_x4(qf[e], sQ + off);
                }
                #pragma unroll
                for (int jn2 = 0; jn2 < 4; jn2++) {
                    const int jA = jn2 * 2, jB = jn2 * 2 + 1;
                    const uint32_t kcom = koff_rowbase + (uint32_t)(ks2 * 32) * 2 + koff_col;
                    uint32_t offA = (uint32_t)(jA * 8 * ASTR) * 2 + kcom;
                    uint32_t offB = (uint32_t)(jB * 8 * ASTR) * 2 + kcom;
                    uint32_t khA[4], khB[4];
                    ldm_x4(khA, sKc + offA); ldm_x4(khB, sKc + offB);
                    mma_f16(sacc[jA], qf[0], khA);     mma_f16(sacc[jB], qf[0], khB);
                    mma_f16(sacc[jA], qf[1], khA + 2); mma_f16(sacc[jB], qf[1], khB + 2);
                }
            }

            if (it >= 2 * qt) {
                int qg0 = q0 + warp * 16 + gid;
                #pragma unroll
                for (int jn = 0; jn < 8; jn++) {
                    int kg = it * 64 + jn * 8 + tig * 2;
                    if (kg > qg0)     sacc[jn][0] = -1e30f;
                    if (kg + 1 > qg0) sacc[jn][1] = -1e30f;
                    if (kg > qg0 + 8)     sacc[jn][2] = -1e30f;
                    if (kg + 1 > qg0 + 8) sacc[jn][3] = -1e30f;
                }
            }

            float mn0 = mrow[0], mn1 = mrow[1];
            #pragma unroll
            for (int jn = 0; jn < 8; jn++) {
                mn0 = fmaxf(mn0, fmaxf(sacc[jn][0], sacc[jn][1]));
                mn1 = fmaxf(mn1, fmaxf(sacc[jn][2], sacc[jn][3]));
            }
            mn0 = fmaxf(mn0, __shfl_xor_sync(0xffffffffu, mn0, 1));
            mn0 = fmaxf(mn0, __shfl_xor_sync(0xffffffffu, mn0, 2));
            mn1 = fmaxf(mn1, __shfl_xor_sync(0xffffffffu, mn1, 1));
            mn1 = fmaxf(mn1, __shfl_xor_sync(0xffffffffu, mn1, 2));
            float al0 = exp2f(mrow[0] - mn0);
            float al1 = exp2f(mrow[1] - mn1);
            mrow[0] = mn0; mrow[1] = mn1;
            lrow[0] *= al0; lrow[1] *= al1;

            uint32_t ph[8][2];
            float lacc0 = 0.0f, lacc1 = 0.0f;
            #pragma unroll
            for (int jn = 0; jn < 8; jn++) {
                uint32_t p0 = ex2_h2(sacc[jn][0] - mn0, sacc[jn][1] - mn0);
                uint32_t p1 = ex2_h2(sacc[jn][2] - mn1, sacc[jn][3] - mn1);
                ph[jn][0] = p0;
                ph[jn][1] = p1;
                float2 f0 = __half22float2(*(__half2*)&p0);
                float2 f1 = __half22float2(*(__half2*)&p1);
                lacc0 += f0.x + f0.y;
                lacc1 += f1.x + f1.y;
            }
            lrow[0] += lacc0;
            lrow[1] += lacc1;

            #pragma unroll
            for (int jd = 0; jd < 16; jd++) {
                oacc[jd][0] *= al0; oacc[jd][1] *= al0;
                oacc[jd][2] *= al1; oacc[jd][3] *= al1;
            }

            #pragma unroll
            for (int kks = 0; kks < 4; kks++) {
                uint32_t aPh[4] = {ph[2 * kks][0], ph[2 * kks][1],
                                   ph[2 * kks + 1][0], ph[2 * kks + 1][1]};
                #pragma unroll
                for (int jd2 = 0; jd2 < 8; jd2++) {
                    uint32_t off = (uint32_t)(kks * 16 * ASTR) * 2 + voff_rowbase +
                                   (uint32_t)(jd2 * 16) * 2 + voff_col;
                    uint32_t vh4[4];
                    ldm_x4_t(vh4, sVc + off);
                    mma_f16(oacc[jd2 * 2], aPh, vh4);
                    mma_f16(oacc[jd2 * 2 + 1], aPh, vh4 + 2);
                }
            }
        }
    }

    lrow[0] += __shfl_xor_sync(0xffffffffu, lrow[0], 1);
    lrow[0] += __shfl_xor_sync(0xffffffffu, lrow[0], 2);
    lrow[1] += __shfl_xor_sync(0xffffffffu, lrow[1], 1);
    lrow[1] += __shfl_xor_sync(0xffffffffu, lrow[1], 2);
    float inv0 = 1.0f / lrow[0];
    float inv1 = 1.0f / lrow[1];

    int row0 = q0 + warp * 16 + gid;
    #pragma unroll
    for (int jd = 0; jd < 16; jd++) {
        int col = h * HD + jd * 8 + tig * 2;
        __half2 h0 = __floats2half2_rn(oacc[jd][0] * inv0, oacc[jd][1] * inv0);
        __half2 h1 = __floats2half2_rn(oacc[jd][2] * inv1, oacc[jd][3] * inv1);
        *(__half2*)(g_ao_h + (size_t)row0 * QD + col)       = h0;
        *(__half2*)(g_ao_h + (size_t)(row0 + 8) * QD + col) = h1;
    }
}

// ---------------------------------------------------------------------------
// launch
// ---------------------------------------------------------------------------
extern "C" void kernel_launch(void* const* d_in, const int* in_sizes, int n_in,
                              void* d_out, int out_size) {
    const float* hidden = (const float*)d_in[0];
    const float* cosb   = (const float*)d_in[1];
    const float* sinb   = (const float*)d_in[2];
    const float* Wq     = (const float*)d_in[3];
    const float* Wk     = (const float*)d_in[4];
    const float* Wv     = (const float*)d_in[5];
    const float* Wo     = (const float*)d_in[6];
    const float* qw     = (const float*)d_in[7];
    const float* kw     = (const float*)d_in[8];
    float* out = (float*)d_out;

    float* qkv_ptr = nullptr;
    __half *hid_h, *wqkv_h, *wo_h, *ao_h;
    cudaGetSymbolAddress((void**)&qkv_ptr, g_qkv);
    cudaGetSymbolAddress((void**)&hid_h, g_hid_h);
    cudaGetSymbolAddress((void**)&wqkv_h, g_wqkv_h);
    cudaGetSymbolAddress((void**)&wo_h, g_wo_h);
    cudaGetSymbolAddress((void**)&ao_h, g_ao_h);

    cudaFuncSetAttribute(gemm_mma, cudaFuncAttributeMaxDynamicSharedMemorySize, GEMM_SMEM);
    cudaFuncSetAttribute(gemm64_mma, cudaFuncAttributeMaxDynamicSharedMemorySize, GEMM64_SMEM);
    cudaFuncSetAttribute(flash_mma_kernel, cudaFuncAttributeMaxDynamicSharedMemorySize, ATTN_SMEM);

    // fused conversions to fp16 (one launch)
    {
        size_t total = (size_t)SEQ * HID + (size_t)QD * HID + 2 * (size_t)KVD * HID +
                       (size_t)HID * QD;
        int nthreads4 = (int)(total / 4);
        cvt_all<<<(nthreads4 + 255) / 256, 256>>>(hidden, Wq, Wk, Wv, Wo);
    }

    // fused QKV projection: g_qkv[2048, 6144] = hidden @ [Wq|Wk|Wv]^T
    gemm_mma<<<dim3(QKVD / 128, SEQ / 128), 256, GEMM_SMEM>>>(
        hid_h, wqkv_h, qkv_ptr, HID, QKVD);

    // RMSNorm + RoPE + fp16 conversion into [h][s][d] buffers
    {
        int nwarps = SEQ * 48;
        int nblocks = (nwarps * 32 + 255) / 256;
        rms_rope_kernel<<<nblocks, 256>>>(cosb, sinb, qw, kw);
    }

    // tensor-core causal GQA flash attention -> g_ao_h
    flash_mma_kernel<<<dim3(NQH, SEQ / 128), 256, ATTN_SMEM>>>();

    // output projection with small M-tiles (640 CTAs -> no wave tail)
    gemm64_mma<<<dim3(HID / 128, SEQ / 64), 256, GEMM64_SMEM>>>(
        ao_h, wo_h, out, QD, HID);
}

// round 16
// speedup vs baseline: 1.2795x; 1.1044x over previous
#include <cuda_runtime.h>
#include <cuda_fp16.h>
#include <cstdint>
#include <cstdio>

#define SEQ   2048
#define HID   2560
#define QD    4096      // 32 heads * 128
#define KVD   1024      // 8 heads * 128
#define QKVD  6144      // QD + 2*KVD
#define HD    128
#define NQH   32
#define NKVH  8

// ---------------------------------------------------------------------------
// Scratch (device globals; no allocation allowed)
// ---------------------------------------------------------------------------
// fp16 operand buffers
__device__ __half g_hid_h[(size_t)SEQ * HID];     // hidden (A of QKV gemm)
__device__ __half g_wqkv_h[(size_t)QKVD * HID];   // Wq|Wk|Wv stacked (B)
__device__ __half g_wo_h[(size_t)HID * QD];       // Wo (B)
__device__ __half g_ao_h[(size_t)SEQ * QD];       // attn out (A of Wo gemm)

// attention operands, [head][seq][128]
__device__ __half g_qh[(size_t)NQH * SEQ * HD];   // Q (scale*log2e folded)
__device__ __half g_kh[(size_t)NKVH * SEQ * HD];  // K
__device__ __half g_vh[(size_t)NKVH * SEQ * HD];  // V

// ---------------------------------------------------------------------------
// PTX helpers
// ---------------------------------------------------------------------------
__device__ __forceinline__ uint32_t smem_u32(const void* p) {
    uint32_t a;
    asm("{ .reg .u64 t; cvta.to.shared.u64 t, %1; cvt.u32.u64 %0, t; }" : "=r"(a) : "l"(p));
    return a;
}
__device__ __forceinline__ void cpa16(uint32_t s, const void* g) {
    asm volatile("cp.async.cg.shared.global [%0], [%1], 16;" :: "r"(s), "l"(g));
}
__device__ __forceinline__ void cpa_commit() {
    asm volatile("cp.async.commit_group;" ::: "memory");
}
__device__ __forceinline__ void cpa_wait1() {
    asm volatile("cp.async.wait_group 1;" ::: "memory");
}
__device__ __forceinline__ void cpa_wait0() {
    asm volatile("cp.async.wait_group 0;" ::: "memory");
}
__device__ __forceinline__ void ldm_x4(uint32_t* r, uint32_t addr) {
    asm volatile("ldmatrix.sync.aligned.m8n8.x4.shared.b16 {%0,%1,%2,%3}, [%4];"
                 : "=r"(r[0]), "=r"(r[1]), "=r"(r[2]), "=r"(r[3]) : "r"(addr));
}
__device__ __forceinline__ void ldm_x4_t(uint32_t* r, uint32_t addr) {
    asm volatile("ldmatrix.sync.aligned.m8n8.x4.trans.shared.b16 {%0,%1,%2,%3}, [%4];"
                 : "=r"(r[0]), "=r"(r[1]), "=r"(r[2]), "=r"(r[3]) : "r"(addr));
}
__device__ __forceinline__ void mma_f16(float* c, const uint32_t* a, const uint32_t* b) {
    asm volatile(
        "mma.sync.aligned.m16n8k16.row.col.f32.f16.f16.f32 "
        "{%0,%1,%2,%3}, {%4,%5,%6,%7}, {%8,%9}, {%0,%1,%2,%3};"
        : "+f"(c[0]), "+f"(c[1]), "+f"(c[2]), "+f"(c[3])
        : "r"(a[0]), "r"(a[1]), "r"(a[2]), "r"(a[3]), "r"(b[0]), "r"(b[1]));
}
__device__ __forceinline__ uint32_t ex2_h2(float a, float b) {
    __half2 t = __floats2half2_rn(a, b);
    uint32_t in = *(uint32_t*)&t, out;
    asm("ex2.approx.f16x2 %0, %1;" : "=r"(out) : "r"(in));
    return out;
}

// ---------------------------------------------------------------------------
// fused fp32 -> fp16 conversion over all 5 input regions (one launch)
// ---------------------------------------------------------------------------
__global__ __launch_bounds__(256)
void cvt_all(const float* __restrict__ hid, const float* __restrict__ wq,
             const float* __restrict__ wk, const float* __restrict__ wv,
             const float* __restrict__ wo) {
    size_t i = ((size_t)blockIdx.x * blockDim.x + threadIdx.x) * 4;
    const size_t n0 = (size_t)SEQ * HID;
    const size_t n1 = (size_t)QD * HID;
    const size_t n2 = (size_t)KVD * HID;
    const size_t n4 = (size_t)HID * QD;

    const float* src;
    __half* dst;
    if (i < n0)                { src = hid; dst = g_hid_h + i; }
    else if ((i -= n0) < n1)   { src = wq;  dst = g_wqkv_h + i; }
    else if ((i -= n1) < n2)   { src = wk;  dst = g_wqkv_h + n1 + i; }
    else if ((i -= n2) < n2)   { src = wv;  dst = g_wqkv_h + n1 + n2 + i; }
    else if ((i -= n2) < n4)   { src = wo;  dst = g_wo_h + i; }
    else return;

    float4 x = *(const float4*)(src + i);
    *(__half2*)(dst)     = __floats2half2_rn(x.x, x.y);
    *(__half2*)(dst + 2) = __floats2half2_rn(x.z, x.w);
}

// ---------------------------------------------------------------------------
// Shared GEMM config (round-13 proven shape)
// CTA 128x128, BK=64, 8 warps (4x2), warp tile 32x64.
// 3-stage cp.async ring, ONE barrier per chunk, 2-chunk prefetch depth.
// ---------------------------------------------------------------------------
#define BK 64
#define LDS_STR 72                    // 64 halves + 8 pad (conflict-free)
#define TILE_H (128 * LDS_STR)
#define STAGE_H (2 * TILE_H)          // A | B
#define GEMM_SMEM (3 * STAGE_H * 2)   // 110592 B

// epilogue staging layout for fused QKV gemm
#define EPI_STR 132                   // floats per staged row

// mainloop body shared via macro-free duplication (two kernels below)

// ---------------------------------------------------------------------------
// Plain GEMM (used for Wo projection): C fp32 output
// ---------------------------------------------------------------------------
__global__ __launch_bounds__(256, 2)
void gemm_mma(const __half* __restrict__ Ah, const __half* __restrict__ Bh,
              float* __restrict__ C, int K, int ldc) {
    extern __shared__ __half smem[];
    const uint32_t sbase = smem_u32(smem);

    const int tid  = threadIdx.x;
    const int warp = tid >> 5;
    const int lane = tid & 31;
    const int wm   = warp & 3;
    const int wn   = warp >> 2;
    const int bx = blockIdx.x, by = blockIdx.y;

    const __half* gA = Ah + (size_t)(by * 128) * K;
    const __half* gB = Bh + (size_t)(bx * 128) * K;

    float acc[2][8][4];
    #pragma unroll
    for (int i = 0; i < 2; i++)
        #pragma unroll
        for (int j = 0; j < 8; j++)
            #pragma unroll
            for (int t = 0; t < 4; t++) acc[i][j][t] = 0.0f;

    const int nchunk = K / BK;
    const int r0 = tid >> 2;
    const int ch0 = (tid & 3) * 8;

    auto load_stage = [&](int c, int s) {
        const size_t koff = (size_t)c * BK;
        uint32_t dst = sbase + (uint32_t)(s * STAGE_H) * 2;
        {
            const __half* a0 = gA + (size_t)r0 * K + koff;
            const __half* a1 = gA + (size_t)(r0 + 64) * K + koff;
            cpa16(dst + (r0 * LDS_STR + ch0) * 2,              a0 + ch0);
            cpa16(dst + (r0 * LDS_STR + ch0 + 32) * 2,         a0 + ch0 + 32);
            cpa16(dst + ((r0 + 64) * LDS_STR + ch0) * 2,       a1 + ch0);
            cpa16(dst + ((r0 + 64) * LDS_STR + ch0 + 32) * 2,  a1 + ch0 + 32);
        }
        {
            uint32_t d = dst + (uint32_t)TILE_H * 2;
            const __half* b0 = gB + (size_t)r0 * K + koff;
            const __half* b1 = gB + (size_t)(r0 + 64) * K + koff;
            cpa16(d + (r0 * LDS_STR + ch0) * 2,              b0 + ch0);
            cpa16(d + (r0 * LDS_STR + ch0 + 32) * 2,         b0 + ch0 + 32);
            cpa16(d + ((r0 + 64) * LDS_STR + ch0) * 2,       b1 + ch0);
            cpa16(d + ((r0 + 64) * LDS_STR + ch0 + 32) * 2,  b1 + ch0 + 32);
        }
    };

    const int a_row = (lane & 7) + ((lane >> 3) & 1) * 8;
    const int a_kof = (lane >> 4) * 8;
    const int b_mat = lane >> 3;
    const int b_row = lane & 7;
    const int b_kof = (b_mat & 1) * 8;
    const int b_jof = (b_mat >> 1);

    load_stage(0, 0);
    cpa_commit();
    load_stage(1, 1);
    cpa_commit();

    int stage = 0;
    for (int c = 0; c < nchunk; c++) {
        if (c == nchunk - 1) cpa_wait0(); else cpa_wait1();
        __syncthreads();
        if (c + 2 < nchunk) {
            int s2 = stage + 2; if (s2 >= 3) s2 -= 3;
            load_stage(c + 2, s2);
            cpa_commit();
        }

        const uint32_t st = sbase + (uint32_t)(stage * STAGE_H) * 2;
        const uint32_t sA = st;
        const uint32_t sB = st + (uint32_t)TILE_H * 2;

        #pragma unroll
        for (int ks = 0; ks < 4; ks++) {
            uint32_t ah[2][4];
            #pragma unroll
            for (int i = 0; i < 2; i++) {
                int m_local = wm * 32 + i * 16 + a_row;
                uint32_t off = (uint32_t)(m_local * LDS_STR + ks * 16 + a_kof) * 2;
                ldm_x4(ah[i], sA + off);
            }
            #pragma unroll
            for (int jp = 0; jp < 4; jp++) {
                int n_local = wn * 64 + (jp * 2 + b_jof) * 8 + b_row;
                uint32_t off = (uint32_t)(n_local * LDS_STR + ks * 16 + b_kof) * 2;
                uint32_t rh[4];
                ldm_x4(rh, sB + off);
                const int j0 = jp * 2, j1 = jp * 2 + 1;
                mma_f16(acc[0][j0], ah[0], rh);   mma_f16(acc[0][j1], ah[0], rh + 2);
                mma_f16(acc[1][j0], ah[1], rh);   mma_f16(acc[1][j1], ah[1], rh + 2);
            }
        }
        if (++stage == 3) stage = 0;
    }

    const int gid = lane >> 2;
    const int tgc = (lane & 3) * 2;
    #pragma unroll
    for (int i = 0; i < 2; i++) {
        int row = by * 128 + wm * 32 + i * 16 + gid;
        #pragma unroll
        for (int j = 0; j < 8; j++) {
            int col = bx * 128 + wn * 64 + j * 8 + tgc;
            float2 v0 = {acc[i][j][0], acc[i][j][1]};
            float2 v1 = {acc[i][j][2], acc[i][j][3]};
            *(float2*)(C + (size_t)row * ldc + col)       = v0;
            *(float2*)(C + (size_t)(row + 8) * ldc + col) = v1;
        }
    }
}

// ---------------------------------------------------------------------------
// QKV GEMM with FUSED RMSNorm + RoPE epilogue.
// bx tile (128 cols) == exactly one head. After mainloop, stage fp32 tile in
// smem, then 8 warps do per-row rms/rope (identical math to old rms_rope
// kernel) writing fp16 directly to g_qh / g_kh / g_vh.
// ---------------------------------------------------------------------------
__global__ __launch_bounds__(256, 2)
void gemm_qkv_mma(const __half* __restrict__ Ah, const __half* __restrict__ Bh,
                  const float* __restrict__ cosb, const float* __restrict__ sinb,
                  const float* __restrict__ qw, const float* __restrict__ kw,
                  int K) {
    extern __shared__ __half smem[];
    const uint32_t sbase = smem_u32(smem);

    const int tid  = threadIdx.x;
    const int warp = tid >> 5;
    const int lane = tid & 31;
    const int wm   = warp & 3;
    const int wn   = warp >> 2;
    const int bx = blockIdx.x, by = blockIdx.y;

    const __half* gA = Ah + (size_t)(by * 128) * K;
    const __half* gB = Bh + (size_t)(bx * 128) * K;

    float acc[2][8][4];
    #pragma unroll
    for (int i = 0; i < 2; i++)
        #pragma unroll
        for (int j = 0; j < 8; j++)
            #pragma unroll
            for (int t = 0; t < 4; t++) acc[i][j][t] = 0.0f;

    const int nchunk = K / BK;
    const int r0 = tid >> 2;
    const int ch0 = (tid & 3) * 8;

    auto load_stage = [&](int c, int s) {
        const size_t koff = (size_t)c * BK;
        uint32_t dst = sbase + (uint32_t)(s * STAGE_H) * 2;
        {
            const __half* a0 = gA + (size_t)r0 * K + koff;
            const __half* a1 = gA + (size_t)(r0 + 64) * K + koff;
            cpa16(dst + (r0 * LDS_STR + ch0) * 2,              a0 + ch0);
            cpa16(dst + (r0 * LDS_STR + ch0 + 32) * 2,         a0 + ch0 + 32);
            cpa16(dst + ((r0 + 64) * LDS_STR + ch0) * 2,       a1 + ch0);
            cpa16(dst + ((r0 + 64) * LDS_STR + ch0 + 32) * 2,  a1 + ch0 + 32);
        }
        {
            uint32_t d = dst + (uint32_t)TILE_H * 2;
            const __half* b0 = gB + (size_t)r0 * K + koff;
            const __half* b1 = gB + (size_t)(r0 + 64) * K + koff;
            cpa16(d + (r0 * LDS_STR + ch0) * 2,              b0 + ch0);
            cpa16(d + (r0 * LDS_STR + ch0 + 32) * 2,         b0 + ch0 + 32);
            cpa16(d + ((r0 + 64) * LDS_STR + ch0) * 2,       b1 + ch0);
            cpa16(d + ((r0 + 64) * LDS_STR + ch0 + 32) * 2,  b1 + ch0 + 32);
        }
    };

    const int a_row = (lane & 7) + ((lane >> 3) & 1) * 8;
    const int a_kof = (lane >> 4) * 8;
    const int b_mat = lane >> 3;
    const int b_row = lane & 7;
    const int b_kof = (b_mat & 1) * 8;
    const int b_jof = (b_mat >> 1);

    load_stage(0, 0);
    cpa_commit();
    load_stage(1, 1);
    cpa_commit();

    int stage = 0;
    for (int c = 0; c < nchunk; c++) {
        if (c == nchunk - 1) cpa_wait0(); else cpa_wait1();
        __syncthreads();
        if (c + 2 < nchunk) {
            int s2 = stage + 2; if (s2 >= 3) s2 -= 3;
            load_stage(c + 2, s2);
            cpa_commit();
        }

        const uint32_t st = sbase + (uint32_t)(stage * STAGE_H) * 2;
        const uint32_t sA = st;
        const uint32_t sB = st + (uint32_t)TILE_H * 2;

        #pragma unroll
        for (int ks = 0; ks < 4; ks++) {
            uint32_t ah[2][4];
            #pragma unroll
            for (int i = 0; i < 2; i++) {
                int m_local = wm * 32 + i * 16 + a_row;
                uint32_t off = (uint32_t)(m_local * LDS_STR + ks * 16 + a_kof) * 2;
                ldm_x4(ah[i], sA + off);
            }
            #pragma unroll
            for (int jp = 0; jp < 4; jp++) {
                int n_local = wn * 64 + (jp * 2 + b_jof) * 8 + b_row;
                uint32_t off = (uint32_t)(n_local * LDS_STR + ks * 16 + b_kof) * 2;
                uint32_t rh[4];
                ldm_x4(rh, sB + off);
                const int j0 = jp * 2, j1 = jp * 2 + 1;
                mma_f16(acc[0][j0], ah[0], rh);   mma_f16(acc[0][j1], ah[0], rh + 2);
                mma_f16(acc[1][j0], ah[1], rh);   mma_f16(acc[1][j1], ah[1], rh + 2);
            }
        }
        if (++stage == 3) stage = 0;
    }

    // ---- fused epilogue: stage tile to smem, then rms/rope per row ----
    __syncthreads();                        // all warps done reading ring
    float* fsm = (float*)smem;              // 128 x EPI_STR floats = 67.6 KB
    {
        const int gid = lane >> 2;
        const int tgc = (lane & 3) * 2;
        #pragma unroll
        for (int i = 0; i < 2; i++) {
            int rr = wm * 32 + i * 16 + gid;
            #pragma unroll
            for (int j = 0; j < 8; j++) {
                int cc = wn * 64 + j * 8 + tgc;
                fsm[rr * EPI_STR + cc]            = acc[i][j][0];
                fsm[rr * EPI_STR + cc + 1]        = acc[i][j][1];
                fsm[(rr + 8) * EPI_STR + cc]      = acc[i][j][2];
                fsm[(rr + 8) * EPI_STR + cc + 1]  = acc[i][j][3];
            }
        }
    }
    __syncthreads();

    const int hh = bx;                      // 0-31 Q, 32-39 K, 40-47 V
    const int d = lane * 4;
    for (int r = warp; r < 128; r += 8) {
        const int s = by * 128 + r;
        float4 x;
        x.x = fsm[r * EPI_STR + d];
        x.y = fsm[r * EPI_STR + d + 1];
        x.z = fsm[r * EPI_STR + d + 2];
        x.w = fsm[r * EPI_STR + d + 3];

        float4 out;
        __half* dsingle;
        if (hh < 40) {
            const float* w;
            if (hh < NQH) {
                w = qw;
                dsingle = g_qh + ((size_t)hh * SEQ + s) * HD;
            } else {
                w = kw;
                dsingle = g_kh + ((size_t)(hh - NQH) * SEQ + s) * HD;
            }
            float ss = x.x * x.x + x.y * x.y + x.z * x.z + x.w * x.w;
            #pragma unroll
            for (int o = 16; o > 0; o >>= 1) ss += __shfl_xor_sync(0xffffffffu, ss, o);
            float rinv = rsqrtf(ss * (1.0f / 128.0f) + 1e-6f);

            float4 wv = *(const float4*)(w + d);
            float4 xn;
            xn.x = x.x * rinv * wv.x; xn.y = x.y * rinv * wv.y;
            xn.z = x.z * rinv * wv.z; xn.w = x.w * rinv * wv.w;

            float4 ot;
            ot.x = __shfl_xor_sync(0xffffffffu, xn.x, 16);
            ot.y = __shfl_xor_sync(0xffffffffu, xn.y, 16);
            ot.z = __shfl_xor_sync(0xffffffffu, xn.z, 16);
            ot.w = __shfl_xor_sync(0xffffffffu, xn.w, 16);
            float sgn = (d < 64) ? -1.0f : 1.0f;

            float4 c = *(const float4*)(cosb + (size_t)s * HD + d);
            float4 si = *(const float4*)(sinb + (size_t)s * HD + d);
            out.x = xn.x * c.x + sgn * ot.x * si.x;
            out.y = xn.y * c.y + sgn * ot.y * si.y;
            out.z = xn.z * c.z + sgn * ot.z * si.z;
            out.w = xn.w * c.w + sgn * ot.w * si.w;
            if (hh < NQH) {
                const float sc = 0.12751743f;   // (1/sqrt(128)) * log2(e)
                out.x *= sc; out.y *= sc; out.z *= sc; out.w *= sc;
            }
        } else {
            out = x;
            dsingle = g_vh + ((size_t)(hh - 40) * SEQ + s) * HD;
        }

        *(__half2*)(dsingle + d)     = __floats2half2_rn(out.x, out.y);
        *(__half2*)(dsingle + d + 2) = __floats2half2_rn(out.z, out.w);
    }
}

// ---------------------------------------------------------------------------
// Tensor-core flash attention, causal, GQA. log2-domain softmax (ex2.f16x2).
// CTA = (head, 128-row q tile), 8 warps. 3-stage KV pipeline.
// ---------------------------------------------------------------------------
#define ASTR 136                   // halves per smem row
#define AKV  (64 * ASTR)           // halves per KV matrix
#define AQ   (128 * ASTR)          // halves per Q matrix
#define ATTN_SMEM ((AQ + 6 * AKV) * 2)   // 139264 B

__global__ __launch_bounds__(256, 1)
void flash_mma_kernel() {
    extern __shared__ __half asm_smem[];
    const uint32_t sb = smem_u32(asm_smem);
    const uint32_t sQ = sb;
    const uint32_t kvb = sQ + AQ * 2;
    const uint32_t sK[3] = { kvb, kvb + 2 * AKV * 2, kvb + 4 * AKV * 2 };
    const uint32_t sV[3] = { kvb + AKV * 2, kvb + 3 * AKV * 2, kvb + 5 * AKV * 2 };

    const int h  = blockIdx.x;
    const int qt = gridDim.y - 1 - blockIdx.y;   // longest tiles first
    const int q0 = qt * 128;
    const int kh = h >> 2;
    const int tid = threadIdx.x;
    const int warp = tid >> 5;
    const int lane = tid & 31;
    const int gid = lane >> 2;
    const int tig = lane & 3;

    const __half* bkh = g_kh + (size_t)kh * SEQ * HD;
    const __half* bvh = g_vh + (size_t)kh * SEQ * HD;

    auto load_kv = [&](int it, int buf) {
        const __half* pk = bkh + (size_t)(it * 64) * HD;
        const __half* pv = bvh + (size_t)(it * 64) * HD;
        #pragma unroll
        for (int i = 0; i < 4; i++) {
            int ch = tid + i * 256;
            int row = ch >> 4, c = ch & 15;
            uint32_t off = (uint32_t)(row * ASTR) * 2 + c * 16;
            size_t goff = (size_t)row * HD + c * 8;
            cpa16(sK[buf] + off, pk + goff);
            cpa16(sV[buf] + off, pv + goff);
        }
    };

    const int nit = 2 * qt + 1;              // KV tiles 0..nit

    {
        const __half* gq = g_qh + ((size_t)h * SEQ + q0) * HD;
        #pragma unroll
        for (int i = 0; i < 8; i++) {
            int ch = tid + i * 256;
            int row = ch >> 4, c = ch & 15;
            uint32_t off = (uint32_t)(row * ASTR) * 2 + c * 16;
            cpa16(sQ + off, gq + (size_t)row * HD + c * 8);
        }
        load_kv(0, 0);
        cpa_commit();
        load_kv(1, 1);
        cpa_commit();
    }

    float oacc[16][4];
    #pragma unroll
    for (int j = 0; j < 16; j++)
        #pragma unroll
        for (int t = 0; t < 4; t++) oacc[j][t] = 0.0f;
    float mrow[2] = {-1e30f, -1e30f};
    float lrow[2] = {0.0f, 0.0f};

    const uint32_t qoff_row = (uint32_t)((warp * 16 + (lane & 15)) * ASTR) * 2;
    const uint32_t qoff_col = (uint32_t)((lane >> 4) * 8) * 2;
    const uint32_t koff_rowbase = (uint32_t)((lane & 7) * ASTR) * 2;
    const uint32_t koff_col = (uint32_t)(((lane >> 3) & 3) * 8) * 2;
    const uint32_t voff_rowbase = (uint32_t)(((lane & 7) + 8 * ((lane >> 3) & 1)) * ASTR) * 2;
    const uint32_t voff_col = (uint32_t)((lane >> 4) * 8) * 2;

    for (int it = 0; it <= nit; it++) {
        const int cur = it % 3;
        if (it == nit) cpa_wait0(); else cpa_wait1();
        __syncthreads();
        if (it + 1 < nit) {
            load_kv(it + 2, (it + 2) % 3);
            cpa_commit();
        }
        const bool active = !(it == nit && warp < 4);
        if (active) {
            const uint32_t sKc = sK[cur];
            const uint32_t sVc = sV[cur];

            float sacc[8][4];
            #pragma unroll
            for (int j = 0; j < 8; j++)
                #pragma unroll
                for (int t = 0; t < 4; t++) sacc[j][t] = 0.0f;

            #pragma unroll
            for (int ks2 = 0; ks2 < 4; ks2++) {
                uint32_t qf[2][4];
                #pragma unroll
                for (int e = 0; e < 2; e++) {
                    uint32_t off = qoff_row + ((uint32_t)((ks2 * 2 + e) * 16) * 2 + qoff_col);
                    ldm_x4(qf[e], sQ + off);
                }
                #pragma unroll
                for (int jn2 = 0; jn2 < 4; jn2++) {
                    const int jA = jn2 * 2, jB = jn2 * 2 + 1;
                    const uint32_t kcom = koff_rowbase + (uint32_t)(ks2 * 32) * 2 + koff_col;
                    uint32_t offA = (uint32_t)(jA * 8 * ASTR) * 2 + kcom;
                    uint32_t offB = (uint32_t)(jB * 8 * ASTR) * 2 + kcom;
                    uint32_t khA[4], khB[4];
                    ldm_x4(khA, sKc + offA); ldm_x4(khB, sKc + offB);
                    mma_f16(sacc[jA], qf[0], khA);     mma_f16(sacc[jB], qf[0], khB);
                    mma_f16(sacc[jA], qf[1], khA + 2); mma_f16(sacc[jB], qf[1], khB + 2);
                }
            }

            if (it >= 2 * qt) {
                int qg0 = q0 + warp * 16 + gid;
                #pragma unroll
                for (int jn = 0; jn < 8; jn++) {
                    int kg = it * 64 + jn * 8 + tig * 2;
                    if (kg > qg0)     sacc[jn][0] = -1e30f;
                    if (kg + 1 > qg0) sacc[jn][1] = -1e30f;
                    if (kg > qg0 + 8)     sacc[jn][2] = -1e30f;
                    if (kg + 1 > qg0 + 8) sacc[jn][3] = -1e30f;
                }
            }

            float mn0 = mrow[0], mn1 = mrow[1];
            #pragma unroll
            for (int jn = 0; jn < 8; jn++) {
                mn0 = fmaxf(mn0, fmaxf(sacc[jn][0], sacc[jn][1]));
                mn1 = fmaxf(mn1, fmaxf(sacc[jn][2], sacc[jn][3]));
            }
            mn0 = fmaxf(mn0, __shfl_xor_sync(0xffffffffu, mn0, 1));
            mn0 = fmaxf(mn0, __shfl_xor_sync(0xffffffffu, mn0, 2));
            mn1 = fmaxf(mn1, __shfl_xor_sync(0xffffffffu, mn1, 1));
            mn1 = fmaxf(mn1, __shfl_xor_sync(0xffffffffu, mn1, 2));
            float al0 = exp2f(mrow[0] - mn0);
            float al1 = exp2f(mrow[1] - mn1);
            mrow[0] = mn0; mrow[1] = mn1;
            lrow[0] *= al0; lrow[1] *= al1;

            uint32_t ph[8][2];
            float lacc0 = 0.0f, lacc1 = 0.0f;
            #pragma unroll
            for (int jn = 0; jn < 8; jn++) {
                uint32_t p0 = ex2_h2(sacc[jn][0] - mn0, sacc[jn][1] - mn0);
                uint32_t p1 = ex2_h2(sacc[jn][2] - mn1, sacc[jn][3] - mn1);
                ph[jn][0] = p0;
                ph[jn][1] = p1;
                float2 f0 = __half22float2(*(__half2*)&p0);
                float2 f1 = __half22float2(*(__half2*)&p1);
                lacc0 += f0.x + f0.y;
                lacc1 += f1.x + f1.y;
            }
            lrow[0] += lacc0;
            lrow[1] += lacc1;

            #pragma unroll
            for (int jd = 0; jd < 16; jd++) {
                oacc[jd][0] *= al0; oacc[jd][1] *= al0;
                oacc[jd][2] *= al1; oacc[jd][3] *= al1;
            }

            #pragma unroll
            for (int kks = 0; kks < 4; kks++) {
                uint32_t aPh[4] = {ph[2 * kks][0], ph[2 * kks][1],
                                   ph[2 * kks + 1][0], ph[2 * kks + 1][1]};
                #pragma unroll
                for (int jd2 = 0; jd2 < 8; jd2++) {
                    uint32_t off = (uint32_t)(kks * 16 * ASTR) * 2 + voff_rowbase +
                                   (uint32_t)(jd2 * 16) * 2 + voff_col;
                    uint32_t vh4[4];
                    ldm_x4_t(vh4, sVc + off);
                    mma_f16(oacc[jd2 * 2], aPh, vh4);
                    mma_f16(oacc[jd2 * 2 + 1], aPh, vh4 + 2);
                }
            }
        }
    }

    lrow[0] += __shfl_xor_sync(0xffffffffu, lrow[0], 1);
    lrow[0] += __shfl_xor_sync(0xffffffffu, lrow[0], 2);
    lrow[1] += __shfl_xor_sync(0xffffffffu, lrow[1], 1);
    lrow[1] += __shfl_xor_sync(0xffffffffu, lrow[1], 2);
    float inv0 = 1.0f / lrow[0];
    float inv1 = 1.0f / lrow[1];

    int row0 = q0 + warp * 16 + gid;
    #pragma unroll
    for (int jd = 0; jd < 16; jd++) {
        int col = h * HD + jd * 8 + tig * 2;
        __half2 h0 = __floats2half2_rn(oacc[jd][0] * inv0, oacc[jd][1] * inv0);
        __half2 h1 = __floats2half2_rn(oacc[jd][2] * inv1, oacc[jd][3] * inv1);
        *(__half2*)(g_ao_h + (size_t)row0 * QD + col)       = h0;
        *(__half2*)(g_ao_h + (size_t)(row0 + 8) * QD + col) = h1;
    }
}

// ---------------------------------------------------------------------------
// launch
// ---------------------------------------------------------------------------
extern "C" void kernel_launch(void* const* d_in, const int* in_sizes, int n_in,
                              void* d_out, int out_size) {
    const float* hidden = (const float*)d_in[0];
    const float* cosb   = (const float*)d_in[1];
    const float* sinb   = (const float*)d_in[2];
    const float* Wq     = (const float*)d_in[3];
    const float* Wk     = (const float*)d_in[4];
    const float* Wv     = (const float*)d_in[5];
    const float* Wo     = (const float*)d_in[6];
    const float* qw     = (const float*)d_in[7];
    const float* kw     = (const float*)d_in[8];
    float* out = (float*)d_out;

    __half *hid_h, *wqkv_h, *wo_h, *ao_h;
    cudaGetSymbolAddress((void**)&hid_h, g_hid_h);
    cudaGetSymbolAddress((void**)&wqkv_h, g_wqkv_h);
    cudaGetSymbolAddress((void**)&wo_h, g_wo_h);
    cudaGetSymbolAddress((void**)&ao_h, g_ao_h);

    cudaFuncSetAttribute(gemm_mma, cudaFuncAttributeMaxDynamicSharedMemorySize, GEMM_SMEM);
    cudaFuncSetAttribute(gemm_qkv_mma, cudaFuncAttributeMaxDynamicSharedMemorySize, GEMM_SMEM);
    cudaFuncSetAttribute(flash_mma_kernel, cudaFuncAttributeMaxDynamicSharedMemorySize, ATTN_SMEM);

    // fused conversions to fp16 (one launch)
    {
        size_t total = (size_t)SEQ * HID + (size_t)QD * HID + 2 * (size_t)KVD * HID +
                       (size_t)HID * QD;
        int nthreads4 = (int)(total / 4);
        cvt_all<<<(nthreads4 + 255) / 256, 256>>>(hidden, Wq, Wk, Wv, Wo);
    }

    // fused QKV projection + RMSNorm + RoPE -> g_qh / g_kh / g_vh (fp16)
    gemm_qkv_mma<<<dim3(QKVD / 128, SEQ / 128), 256, GEMM_SMEM>>>(
        hid_h, wqkv_h, cosb, sinb, qw, kw, HID);

    // tensor-core causal GQA flash attention -> g_ao_h
    flash_mma_kernel<<<dim3(NQH, SEQ / 128), 256, ATTN_SMEM>>>();

    // output projection: out[2048, 2560] = O @ Wo^T
    gemm_mma<<<dim3(HID / 128, SEQ / 128), 256, GEMM_SMEM>>>(
        ao_h, wo_h, out, QD, HID);
}

// round 17
// speedup vs baseline: 1.2967x; 1.0135x over previous
#include <cuda_runtime.h>
#include <cuda_fp16.h>
#include <cstdint>
#include <cstdio>

#define SEQ   2048
#define HID   2560
#define QD    4096      // 32 heads * 128
#define KVD   1024      // 8 heads * 128
#define QKVD  6144      // QD + 2*KVD
#define HD    128
#define NQH   32
#define NKVH  8

// ---------------------------------------------------------------------------
// Scratch (device globals; no allocation allowed)
// ---------------------------------------------------------------------------
// fp16 operand buffers
__device__ __half g_hid_h[(size_t)SEQ * HID];     // hidden (A of QKV gemm)
__device__ __half g_wqkv_h[(size_t)QKVD * HID];   // Wq|Wk|Wv stacked (B)
__device__ __half g_wo_h[(size_t)HID * QD];       // Wo (B)
__device__ __half g_ao_h[(size_t)SEQ * QD];       // attn out (A of Wo gemm)

// attention operands, [head][seq][128]
__device__ __half g_qh[(size_t)NQH * SEQ * HD];   // Q (scale*log2e folded)
__device__ __half g_kh[(size_t)NKVH * SEQ * HD];  // K
__device__ __half g_vh[(size_t)NKVH * SEQ * HD];  // V

// ---------------------------------------------------------------------------
// PTX helpers
// ---------------------------------------------------------------------------
__device__ __forceinline__ uint32_t smem_u32(const void* p) {
    uint32_t a;
    asm("{ .reg .u64 t; cvta.to.shared.u64 t, %1; cvt.u32.u64 %0, t; }" : "=r"(a) : "l"(p));
    return a;
}
__device__ __forceinline__ void cpa16(uint32_t s, const void* g) {
    asm volatile("cp.async.cg.shared.global [%0], [%1], 16;" :: "r"(s), "l"(g));
}
__device__ __forceinline__ void cpa_commit() {
    asm volatile("cp.async.commit_group;" ::: "memory");
}
__device__ __forceinline__ void cpa_wait1() {
    asm volatile("cp.async.wait_group 1;" ::: "memory");
}
__device__ __forceinline__ void cpa_wait0() {
    asm volatile("cp.async.wait_group 0;" ::: "memory");
}
__device__ __forceinline__ void ldm_x4(uint32_t* r, uint32_t addr) {
    asm volatile("ldmatrix.sync.aligned.m8n8.x4.shared.b16 {%0,%1,%2,%3}, [%4];"
                 : "=r"(r[0]), "=r"(r[1]), "=r"(r[2]), "=r"(r[3]) : "r"(addr));
}
__device__ __forceinline__ void ldm_x4_t(uint32_t* r, uint32_t addr) {
    asm volatile("ldmatrix.sync.aligned.m8n8.x4.trans.shared.b16 {%0,%1,%2,%3}, [%4];"
                 : "=r"(r[0]), "=r"(r[1]), "=r"(r[2]), "=r"(r[3]) : "r"(addr));
}
__device__ __forceinline__ void mma_f16(float* c, const uint32_t* a, const uint32_t* b) {
    asm volatile(
        "mma.sync.aligned.m16n8k16.row.col.f32.f16.f16.f32 "
        "{%0,%1,%2,%3}, {%4,%5,%6,%7}, {%8,%9}, {%0,%1,%2,%3};"
        : "+f"(c[0]), "+f"(c[1]), "+f"(c[2]), "+f"(c[3])
        : "r"(a[0]), "r"(a[1]), "r"(a[2]), "r"(a[3]), "r"(b[0]), "r"(b[1]));
}
__device__ __forceinline__ uint32_t ex2_h2(float a, float b) {
    __half2 t = __floats2half2_rn(a, b);
    uint32_t in = *(uint32_t*)&t, out;
    asm("ex2.approx.f16x2 %0, %1;" : "=r"(out) : "r"(in));
    return out;
}

// ---------------------------------------------------------------------------
// fused fp32 -> fp16 conversion, 16 elems/thread (4 independent float4 loads
// -> MLP=4). All region sizes are multiples of 16 so a 16-aligned chunk never
// straddles a region boundary.
// ---------------------------------------------------------------------------
__global__ __launch_bounds__(256)
void cvt_all(const float* __restrict__ hid, const float* __restrict__ wq,
             const float* __restrict__ wk, const float* __restrict__ wv,
             const float* __restrict__ wo) {
    size_t i = ((size_t)blockIdx.x * blockDim.x + threadIdx.x) * 16;
    const size_t n0 = (size_t)SEQ * HID;
    const size_t n1 = (size_t)QD * HID;
    const size_t n2 = (size_t)KVD * HID;
    const size_t n4 = (size_t)HID * QD;

    const float* src;
    __half* dst;
    if (i < n0)                { src = hid + i; dst = g_hid_h + i; }
    else if ((i -= n0) < n1)   { src = wq + i;  dst = g_wqkv_h + i; }
    else if ((i -= n1) < n2)   { src = wk + i;  dst = g_wqkv_h + n1 + i; }
    else if ((i -= n2) < n2)   { src = wv + i;  dst = g_wqkv_h + n1 + n2 + i; }
    else if ((i -= n2) < n4)   { src = wo + i;  dst = g_wo_h + i; }
    else return;

    float4 x0 = *(const float4*)(src);
    float4 x1 = *(const float4*)(src + 4);
    float4 x2 = *(const float4*)(src + 8);
    float4 x3 = *(const float4*)(src + 12);

    __half2 h[8];
    h[0] = __floats2half2_rn(x0.x, x0.y);
    h[1] = __floats2half2_rn(x0.z, x0.w);
    h[2] = __floats2half2_rn(x1.x, x1.y);
    h[3] = __floats2half2_rn(x1.z, x1.w);
    h[4] = __floats2half2_rn(x2.x, x2.y);
    h[5] = __floats2half2_rn(x2.z, x2.w);
    h[6] = __floats2half2_rn(x3.x, x3.y);
    h[7] = __floats2half2_rn(x3.z, x3.w);
    *(uint4*)(dst)     = *(uint4*)&h[0];   // 16B store (8 halves)
    *(uint4*)(dst + 8) = *(uint4*)&h[4];
}

// ---------------------------------------------------------------------------
// Shared GEMM config (round-13 proven shape)
// CTA 128x128, BK=64, 8 warps (4x2), warp tile 32x64.
// 3-stage cp.async ring, ONE barrier per chunk, 2-chunk prefetch depth.
// ---------------------------------------------------------------------------
#define BK 64
#define LDS_STR 72                    // 64 halves + 8 pad (conflict-free)
#define TILE_H (128 * LDS_STR)
#define STAGE_H (2 * TILE_H)          // A | B
#define GEMM_SMEM (3 * STAGE_H * 2)   // 110592 B

// epilogue staging layout for fused QKV gemm
#define EPI_STR 132                   // floats per staged row

// ---------------------------------------------------------------------------
// Plain GEMM (used for Wo projection): C fp32 output
// ---------------------------------------------------------------------------
__global__ __launch_bounds__(256, 2)
void gemm_mma(const __half* __restrict__ Ah, const __half* __restrict__ Bh,
              float* __restrict__ C, int K, int ldc) {
    extern __shared__ __half smem[];
    const uint32_t sbase = smem_u32(smem);

    const int tid  = threadIdx.x;
    const int warp = tid >> 5;
    const int lane = tid & 31;
    const int wm   = warp & 3;
    const int wn   = warp >> 2;
    const int bx = blockIdx.x, by = blockIdx.y;

    const __half* gA = Ah + (size_t)(by * 128) * K;
    const __half* gB = Bh + (size_t)(bx * 128) * K;

    float acc[2][8][4];
    #pragma unroll
    for (int i = 0; i < 2; i++)
        #pragma unroll
        for (int j = 0; j < 8; j++)
            #pragma unroll
            for (int t = 0; t < 4; t++) acc[i][j][t] = 0.0f;

    const int nchunk = K / BK;
    const int r0 = tid >> 2;
    const int ch0 = (tid & 3) * 8;

    auto load_stage = [&](int c, int s) {
        const size_t koff = (size_t)c * BK;
        uint32_t dst = sbase + (uint32_t)(s * STAGE_H) * 2;
        {
            const __half* a0 = gA + (size_t)r0 * K + koff;
            const __half* a1 = gA + (size_t)(r0 + 64) * K + koff;
            cpa16(dst + (r0 * LDS_STR + ch0) * 2,              a0 + ch0);
            cpa16(dst + (r0 * LDS_STR + ch0 + 32) * 2,         a0 + ch0 + 32);
            cpa16(dst + ((r0 + 64) * LDS_STR + ch0) * 2,       a1 + ch0);
            cpa16(dst + ((r0 + 64) * LDS_STR + ch0 + 32) * 2,  a1 + ch0 + 32);
        }
        {
            uint32_t d = dst + (uint32_t)TILE_H * 2;
            const __half* b0 = gB + (size_t)r0 * K + koff;
            const __half* b1 = gB + (size_t)(r0 + 64) * K + koff;
            cpa16(d + (r0 * LDS_STR + ch0) * 2,              b0 + ch0);
            cpa16(d + (r0 * LDS_STR + ch0 + 32) * 2,         b0 + ch0 + 32);
            cpa16(d + ((r0 + 64) * LDS_STR + ch0) * 2,       b1 + ch0);
            cpa16(d + ((r0 + 64) * LDS_STR + ch0 + 32) * 2,  b1 + ch0 + 32);
        }
    };

    const int a_row = (lane & 7) + ((lane >> 3) & 1) * 8;
    const int a_kof = (lane >> 4) * 8;
    const int b_mat = lane >> 3;
    const int b_row = lane & 7;
    const int b_kof = (b_mat & 1) * 8;
    const int b_jof = (b_mat >> 1);

    load_stage(0, 0);
    cpa_commit();
    load_stage(1, 1);
    cpa_commit();

    int stage = 0;
    for (int c = 0; c < nchunk; c++) {
        if (c == nchunk - 1) cpa_wait0(); else cpa_wait1();
        __syncthreads();
        if (c + 2 < nchunk) {
            int s2 = stage + 2; if (s2 >= 3) s2 -= 3;
            load_stage(c + 2, s2);
            cpa_commit();
        }

        const uint32_t st = sbase + (uint32_t)(stage * STAGE_H) * 2;
        const uint32_t sA = st;
        const uint32_t sB = st + (uint32_t)TILE_H * 2;

        #pragma unroll
        for (int ks = 0; ks < 4; ks++) {
            uint32_t ah[2][4];
            #pragma unroll
            for (int i = 0; i < 2; i++) {
                int m_local = wm * 32 + i * 16 + a_row;
                uint32_t off = (uint32_t)(m_local * LDS_STR + ks * 16 + a_kof) * 2;
                ldm_x4(ah[i], sA + off);
            }
            #pragma unroll
            for (int jp = 0; jp < 4; jp++) {
                int n_local = wn * 64 + (jp * 2 + b_jof) * 8 + b_row;
                uint32_t off = (uint32_t)(n_local * LDS_STR + ks * 16 + b_kof) * 2;
                uint32_t rh[4];
                ldm_x4(rh, sB + off);
                const int j0 = jp * 2, j1 = jp * 2 + 1;
                mma_f16(acc[0][j0], ah[0], rh);   mma_f16(acc[0][j1], ah[0], rh + 2);
                mma_f16(acc[1][j0], ah[1], rh);   mma_f16(acc[1][j1], ah[1], rh + 2);
            }
        }
        if (++stage == 3) stage = 0;
    }

    const int gid = lane >> 2;
    const int tgc = (lane & 3) * 2;
    #pragma unroll
    for (int i = 0; i < 2; i++) {
        int row = by * 128 + wm * 32 + i * 16 + gid;
        #pragma unroll
        for (int j = 0; j < 8; j++) {
            int col = bx * 128 + wn * 64 + j * 8 + tgc;
            float2 v0 = {acc[i][j][0], acc[i][j][1]};
            float2 v1 = {acc[i][j][2], acc[i][j][3]};
            *(float2*)(C + (size_t)row * ldc + col)       = v0;
            *(float2*)(C + (size_t)(row + 8) * ldc + col) = v1;
        }
    }
}

// ---------------------------------------------------------------------------
// QKV GEMM with FUSED RMSNorm + RoPE epilogue.
// ---------------------------------------------------------------------------
__global__ __launch_bounds__(256, 2)
void gemm_qkv_mma(const __half* __restrict__ Ah, const __half* __restrict__ Bh,
                  const float* __restrict__ cosb, const float* __restrict__ sinb,
                  const float* __restrict__ qw, const float* __restrict__ kw,
                  int K) {
    extern __shared__ __half smem[];
    const uint32_t sbase = smem_u32(smem);

    const int tid  = threadIdx.x;
    const int warp = tid >> 5;
    const int lane = tid & 31;
    const int wm   = warp & 3;
    const int wn   = warp >> 2;
    const int bx = blockIdx.x, by = blockIdx.y;

    const __half* gA = Ah + (size_t)(by * 128) * K;
    const __half* gB = Bh + (size_t)(bx * 128) * K;

    float acc[2][8][4];
    #pragma unroll
    for (int i = 0; i < 2; i++)
        #pragma unroll
        for (int j = 0; j < 8; j++)
            #pragma unroll
            for (int t = 0; t < 4; t++) acc[i][j][t] = 0.0f;

    const int nchunk = K / BK;
    const int r0 = tid >> 2;
    const int ch0 = (tid & 3) * 8;

    auto load_stage = [&](int c, int s) {
        const size_t koff = (size_t)c * BK;
        uint32_t dst = sbase + (uint32_t)(s * STAGE_H) * 2;
        {
            const __half* a0 = gA + (size_t)r0 * K + koff;
            const __half* a1 = gA + (size_t)(r0 + 64) * K + koff;
            cpa16(dst + (r0 * LDS_STR + ch0) * 2,              a0 + ch0);
            cpa16(dst + (r0 * LDS_STR + ch0 + 32) * 2,         a0 + ch0 + 32);
            cpa16(dst + ((r0 + 64) * LDS_STR + ch0) * 2,       a1 + ch0);
            cpa16(dst + ((r0 + 64) * LDS_STR + ch0 + 32) * 2,  a1 + ch0 + 32);
        }
        {
            uint32_t d = dst + (uint32_t)TILE_H * 2;
            const __half* b0 = gB + (size_t)r0 * K + koff;
            const __half* b1 = gB + (size_t)(r0 + 64) * K + koff;
            cpa16(d + (r0 * LDS_STR + ch0) * 2,              b0 + ch0);
            cpa16(d + (r0 * LDS_STR + ch0 + 32) * 2,         b0 + ch0 + 32);
            cpa16(d + ((r0 + 64) * LDS_STR + ch0) * 2,       b1 + ch0);
            cpa16(d + ((r0 + 64) * LDS_STR + ch0 + 32) * 2,  b1 + ch0 + 32);
        }
    };

    const int a_row = (lane & 7) + ((lane >> 3) & 1) * 8;
    const int a_kof = (lane >> 4) * 8;
    const int b_mat = lane >> 3;
    const int b_row = lane & 7;
    const int b_kof = (b_mat & 1) * 8;
    const int b_jof = (b_mat >> 1);

    load_stage(0, 0);
    cpa_commit();
    load_stage(1, 1);
    cpa_commit();

    int stage = 0;
    for (int c = 0; c < nchunk; c++) {
        if (c == nchunk - 1) cpa_wait0(); else cpa_wait1();
        __syncthreads();
        if (c + 2 < nchunk) {
            int s2 = stage + 2; if (s2 >= 3) s2 -= 3;
            load_stage(c + 2, s2);
            cpa_commit();
        }

        const uint32_t st = sbase + (uint32_t)(stage * STAGE_H) * 2;
        const uint32_t sA = st;
        const uint32_t sB = st + (uint32_t)TILE_H * 2;

        #pragma unroll
        for (int ks = 0; ks < 4; ks++) {
            uint32_t ah[2][4];
            #pragma unroll
            for (int i = 0; i < 2; i++) {
                int m_local = wm * 32 + i * 16 + a_row;
                uint32_t off = (uint32_t)(m_local * LDS_STR + ks * 16 + a_kof) * 2;
                ldm_x4(ah[i], sA + off);
            }
            #pragma unroll
            for (int jp = 0; jp < 4; jp++) {
                int n_local = wn * 64 + (jp * 2 + b_jof) * 8 + b_row;
                uint32_t off = (uint32_t)(n_local * LDS_STR + ks * 16 + b_kof) * 2;
                uint32_t rh[4];
                ldm_x4(rh, sB + off);
                const int j0 = jp * 2, j1 = jp * 2 + 1;
                mma_f16(acc[0][j0], ah[0], rh);   mma_f16(acc[0][j1], ah[0], rh + 2);
                mma_f16(acc[1][j0], ah[1], rh);   mma_f16(acc[1][j1], ah[1], rh + 2);
            }
        }
        if (++stage == 3) stage = 0;
    }

    // ---- fused epilogue: stage tile to smem, then rms/rope per row ----
    __syncthreads();
    float* fsm = (float*)smem;
    {
        const int gid = lane >> 2;
        const int tgc = (lane & 3) * 2;
        #pragma unroll
        for (int i = 0; i < 2; i++) {
            int rr = wm * 32 + i * 16 + gid;
            #pragma unroll
            for (int j = 0; j < 8; j++) {
                int cc = wn * 64 + j * 8 + tgc;
                fsm[rr * EPI_STR + cc]            = acc[i][j][0];
                fsm[rr * EPI_STR + cc + 1]        = acc[i][j][1];
                fsm[(rr + 8) * EPI_STR + cc]      = acc[i][j][2];
                fsm[(rr + 8) * EPI_STR + cc + 1]  = acc[i][j][3];
            }
        }
    }
    __syncthreads();

    const int hh = bx;                      // 0-31 Q, 32-39 K, 40-47 V
    const int d = lane * 4;
    for (int r = warp; r < 128; r += 8) {
        const int s = by * 128 + r;
        float4 x;
        x.x = fsm[r * EPI_STR + d];
        x.y = fsm[r * EPI_STR + d + 1];
        x.z = fsm[r * EPI_STR + d + 2];
        x.w = fsm[r * EPI_STR + d + 3];

        float4 out;
        __half* dsingle;
        if (hh < 40) {
            const float* w;
            if (hh < NQH) {
                w = qw;
                dsingle = g_qh + ((size_t)hh * SEQ + s) * HD;
            } else {
                w = kw;
                dsingle = g_kh + ((size_t)(hh - NQH) * SEQ + s) * HD;
            }
            float ss = x.x * x.x + x.y * x.y + x.z * x.z + x.w * x.w;
            #pragma unroll
            for (int o = 16; o > 0; o >>= 1) ss += __shfl_xor_sync(0xffffffffu, ss, o);
            float rinv = rsqrtf(ss * (1.0f / 128.0f) + 1e-6f);

            float4 wv = *(const float4*)(w + d);
            float4 xn;
            xn.x = x.x * rinv * wv.x; xn.y = x.y * rinv * wv.y;
            xn.z = x.z * rinv * wv.z; xn.w = x.w * rinv * wv.w;

            float4 ot;
            ot.x = __shfl_xor_sync(0xffffffffu, xn.x, 16);
            ot.y = __shfl_xor_sync(0xffffffffu, xn.y, 16);
            ot.z = __shfl_xor_sync(0xffffffffu, xn.z, 16);
            ot.w = __shfl_xor_sync(0xffffffffu, xn.w, 16);
            float sgn = (d < 64) ? -1.0f : 1.0f;

            float4 c = *(const float4*)(cosb + (size_t)s * HD + d);
            float4 si = *(const float4*)(sinb + (size_t)s * HD + d);
            out.x = xn.x * c.x + sgn * ot.x * si.x;
            out.y = xn.y * c.y + sgn * ot.y * si.y;
            out.z = xn.z * c.z + sgn * ot.z * si.z;
            out.w = xn.w * c.w + sgn * ot.w * si.w;
            if (hh < NQH) {
                const float sc = 0.12751743f;   // (1/sqrt(128)) * log2(e)
                out.x *= sc; out.y *= sc; out.z *= sc; out.w *= sc;
            }
        } else {
            out = x;
            dsingle = g_vh + ((size_t)(hh - 40) * SEQ + s) * HD;
        }

        *(__half2*)(dsingle + d)     = __floats2half2_rn(out.x, out.y);
        *(__half2*)(dsingle + d + 2) = __floats2half2_rn(out.z, out.w);
    }
}

// ---------------------------------------------------------------------------
// Tensor-core flash attention, causal, GQA. log2-domain softmax (ex2.f16x2).
// CTA = (head, 128-row q tile), 8 warps. 3-stage KV pipeline.
// ---------------------------------------------------------------------------
#define ASTR 136                   // halves per smem row
#define AKV  (64 * ASTR)           // halves per KV matrix
#define AQ   (128 * ASTR)          // halves per Q matrix
#define ATTN_SMEM ((AQ + 6 * AKV) * 2)   // 139264 B

__global__ __launch_bounds__(256, 1)
void flash_mma_kernel() {
    extern __shared__ __half asm_smem[];
    const uint32_t sb = smem_u32(asm_smem);
    const uint32_t sQ = sb;
    const uint32_t kvb = sQ + AQ * 2;
    const uint32_t sK[3] = { kvb, kvb + 2 * AKV * 2, kvb + 4 * AKV * 2 };
    const uint32_t sV[3] = { kvb + AKV * 2, kvb + 3 * AKV * 2, kvb + 5 * AKV * 2 };

    const int h  = blockIdx.x;
    const int qt = gridDim.y - 1 - blockIdx.y;   // longest tiles first
    const int q0 = qt * 128;
    const int kh = h >> 2;
    const int tid = threadIdx.x;
    const int warp = tid >> 5;
    const int lane = tid & 31;
    const int gid = lane >> 2;
    const int tig = lane & 3;

    const __half* bkh = g_kh + (size_t)kh * SEQ * HD;
    const __half* bvh = g_vh + (size_t)kh * SEQ * HD;

    auto load_kv = [&](int it, int buf) {
        const __half* pk = bkh + (size_t)(it * 64) * HD;
        const __half* pv = bvh + (size_t)(it * 64) * HD;
        #pragma unroll
        for (int i = 0; i < 4; i++) {
            int ch = tid + i * 256;
            int row = ch >> 4, c = ch & 15;
            uint32_t off = (uint32_t)(row * ASTR) * 2 + c * 16;
            size_t goff = (size_t)row * HD + c * 8;
            cpa16(sK[buf] + off, pk + goff);
            cpa16(sV[buf] + off, pv + goff);
        }
    };

    const int nit = 2 * qt + 1;              // KV tiles 0..nit

    {
        const __half* gq = g_qh + ((size_t)h * SEQ + q0) * HD;
        #pragma unroll
        for (int i = 0; i < 8; i++) {
            int ch = tid + i * 256;
            int row = ch >> 4, c = ch & 15;
            uint32_t off = (uint32_t)(row * ASTR) * 2 + c * 16;
            cpa16(sQ + off, gq + (size_t)row * HD + c * 8);
        }
        load_kv(0, 0);
        cpa_commit();
        load_kv(1, 1);
        cpa_commit();
    }

    float oacc[16][4];
    #pragma unroll
    for (int j = 0; j < 16; j++)
        #pragma unroll
        for (int t = 0; t < 4; t++) oacc[j][t] = 0.0f;
    float mrow[2] = {-1e30f, -1e30f};
    float lrow[2] = {0.0f, 0.0f};

    const uint32_t qoff_row = (uint32_t)((warp * 16 + (lane & 15)) * ASTR) * 2;
    const uint32_t qoff_col = (uint32_t)((lane >> 4) * 8) * 2;
    const uint32_t koff_rowbase = (uint32_t)((lane & 7) * ASTR) * 2;
    const uint32_t koff_col = (uint32_t)(((lane >> 3) & 3) * 8) * 2;
    const uint32_t voff_rowbase = (uint32_t)(((lane & 7) + 8 * ((lane >> 3) & 1)) * ASTR) * 2;
    const uint32_t voff_col = (uint32_t)((lane >> 4) * 8) * 2;

    for (int it = 0; it <= nit; it++) {
        const int cur = it % 3;
        if (it == nit) cpa_wait0(); else cpa_wait1();
        __syncthreads();
        if (it + 1 < nit) {
            load_kv(it + 2, (it + 2) % 3);
            cpa_commit();
        }
        const bool active = !(it == nit && warp < 4);
        if (active) {
            const uint32_t sKc = sK[cur];
            const uint32_t sVc = sV[cur];

            float sacc[8][4];
            #pragma unroll
            for (int j = 0; j < 8; j++)
                #pragma unroll
                for (int t = 0; t < 4; t++) sacc[j][t] = 0.0f;

            #pragma unroll
            for (int ks2 = 0; ks2 < 4; ks2++) {
                uint32_t qf[2][4];
                #pragma unroll
                for (int e = 0; e < 2; e++) {
                    uint32_t off = qoff_row + ((uint32_t)((ks2 * 2 + e) * 16) * 2 + qoff_col);
                    ldm_x4(qf[e], sQ + off);
                }
                #pragma unroll
                for (int jn2 = 0; jn2 < 4; jn2++) {
                    const int jA = jn2 * 2, jB = jn2 * 2 + 1;
                    const uint32_t kcom = koff_rowbase + (uint32_t)(ks2 * 32) * 2 + koff_col;
                    uint32_t offA = (uint32_t)(jA * 8 * ASTR) * 2 + kcom;
                    uint32_t offB = (uint32_t)(jB * 8 * ASTR) * 2 + kcom;
                    uint32_t khA[4], khB[4];
                    ldm_x4(khA, sKc + offA); ldm_x4(khB, sKc + offB);
                    mma_f16(sacc[jA], qf[0], khA);     mma_f16(sacc[jB], qf[0], khB);
                    mma_f16(sacc[jA], qf[1], khA + 2); mma_f16(sacc[jB], qf[1], khB + 2);
                }
            }

            if (it >= 2 * qt) {
                int qg0 = q0 + warp * 16 + gid;
                #pragma unroll
                for (int jn = 0; jn < 8; jn++) {
                    int kg = it * 64 + jn * 8 + tig * 2;
                    if (kg > qg0)     sacc[jn][0] = -1e30f;
                    if (kg + 1 > qg0) sacc[jn][1] = -1e30f;
                    if (kg > qg0 + 8)     sacc[jn][2] = -1e30f;
                    if (kg + 1 > qg0 + 8) sacc[jn][3] = -1e30f;
                }
            }

            float mn0 = mrow[0], mn1 = mrow[1];
            #pragma unroll
            for (int jn = 0; jn < 8; jn++) {
                mn0 = fmaxf(mn0, fmaxf(sacc[jn][0], sacc[jn][1]));
                mn1 = fmaxf(mn1, fmaxf(sacc[jn][2], sacc[jn][3]));
            }
            mn0 = fmaxf(mn0, __shfl_xor_sync(0xffffffffu, mn0, 1));
            mn0 = fmaxf(mn0, __shfl_xor_sync(0xffffffffu, mn0, 2));
            mn1 = fmaxf(mn1, __shfl_xor_sync(0xffffffffu, mn1, 1));
            mn1 = fmaxf(mn1, __shfl_xor_sync(0xffffffffu, mn1, 2));
            float al0 = exp2f(mrow[0] - mn0);
            float al1 = exp2f(mrow[1] - mn1);
            mrow[0] = mn0; mrow[1] = mn1;
            lrow[0] *= al0; lrow[1] *= al1;

            uint32_t ph[8][2];
            float lacc0 = 0.0f, lacc1 = 0.0f;
            #pragma unroll
            for (int jn = 0; jn < 8; jn++) {
                uint32_t p0 = ex2_h2(sacc[jn][0] - mn0, sacc[jn][1] - mn0);
                uint32_t p1 = ex2_h2(sacc[jn][2] - mn1, sacc[jn][3] - mn1);
                ph[jn][0] = p0;
                ph[jn][1] = p1;
                float2 f0 = __half22float2(*(__half2*)&p0);
                float2 f1 = __half22float2(*(__half2*)&p1);
                lacc0 += f0.x + f0.y;
                lacc1 += f1.x + f1.y;
            }
            lrow[0] += lacc0;
            lrow[1] += lacc1;

            #pragma unroll
            for (int jd = 0; jd < 16; jd++) {
                oacc[jd][0] *= al0; oacc[jd][1] *= al0;
                oacc[jd][2] *= al1; oacc[jd][3] *= al1;
            }

            #pragma unroll
            for (int kks = 0; kks < 4; kks++) {
                uint32_t aPh[4] = {ph[2 * kks][0], ph[2 * kks][1],
                                   ph[2 * kks + 1][0], ph[2 * kks + 1][1]};
                #pragma unroll
                for (int jd2 = 0; jd2 < 8; jd2++) {
                    uint32_t off = (uint32_t)(kks * 16 * ASTR) * 2 + voff_rowbase +
                                   (uint32_t)(jd2 * 16) * 2 + voff_col;
                    uint32_t vh4[4];
                    ldm_x4_t(vh4, sVc + off);
                    mma_f16(oacc[jd2 * 2], aPh, vh4);
                    mma_f16(oacc[jd2 * 2 + 1], aPh, vh4 + 2);
                }
            }
        }
    }

    lrow[0] += __shfl_xor_sync(0xffffffffu, lrow[0], 1);
    lrow[0] += __shfl_xor_sync(0xffffffffu, lrow[0], 2);
    lrow[1] += __shfl_xor_sync(0xffffffffu, lrow[1], 1);
    lrow[1] += __shfl_xor_sync(0xffffffffu, lrow[1], 2);
    float inv0 = 1.0f / lrow[0];
    float inv1 = 1.0f / lrow[1];

    int row0 = q0 + warp * 16 + gid;
    #pragma unroll
    for (int jd = 0; jd < 16; jd++) {
        int col = h * HD + jd * 8 + tig * 2;
        __half2 h0 = __floats2half2_rn(oacc[jd][0] * inv0, oacc[jd][1] * inv0);
        __half2 h1 = __floats2half2_rn(oacc[jd][2] * inv1, oacc[jd][3] * inv1);
        *(__half2*)(g_ao_h + (size_t)row0 * QD + col)       = h0;
        *(__half2*)(g_ao_h + (size_t)(row0 + 8) * QD + col) = h1;
    }
}

// ---------------------------------------------------------------------------
// launch
// ---------------------------------------------------------------------------
extern "C" void kernel_launch(void* const* d_in, const int* in_sizes, int n_in,
                              void* d_out, int out_size) {
    const float* hidden = (const float*)d_in[0];
    const float* cosb   = (const float*)d_in[1];
    const float* sinb   = (const float*)d_in[2];
    const float* Wq     = (const float*)d_in[3];
    const float* Wk     = (const float*)d_in[4];
    const float* Wv     = (const float*)d_in[5];
    const float* Wo     = (const float*)d_in[6];
    const float* qw     = (const float*)d_in[7];
    const float* kw     = (const float*)d_in[8];
    float* out = (float*)d_out;

    __half *hid_h, *wqkv_h, *wo_h, *ao_h;
    cudaGetSymbolAddress((void**)&hid_h, g_hid_h);
    cudaGetSymbolAddress((void**)&wqkv_h, g_wqkv_h);
    cudaGetSymbolAddress((void**)&wo_h, g_wo_h);
    cudaGetSymbolAddress((void**)&ao_h, g_ao_h);

    cudaFuncSetAttribute(gemm_mma, cudaFuncAttributeMaxDynamicSharedMemorySize, GEMM_SMEM);
    cudaFuncSetAttribute(gemm_qkv_mma, cudaFuncAttributeMaxDynamicSharedMemorySize, GEMM_SMEM);
    cudaFuncSetAttribute(flash_mma_kernel, cudaFuncAttributeMaxDynamicSharedMemorySize, ATTN_SMEM);

    // fused conversions to fp16 (one launch, 16 elems/thread, MLP=4)
    {
        size_t total = (size_t)SEQ * HID + (size_t)QD * HID + 2 * (size_t)KVD * HID +
                       (size_t)HID * QD;           // 31,457,280
        int nthreads16 = (int)(total / 16);
        cvt_all<<<(nthreads16 + 255) / 256, 256>>>(hidden, Wq, Wk, Wv, Wo);
    }

    // fused QKV projection + RMSNorm + RoPE -> g_qh / g_kh / g_vh (fp16)
    gemm_qkv_mma<<<dim3(QKVD / 128, SEQ / 128), 256, GEMM_SMEM>>>(
        hid_h, wqkv_h, cosb, sinb, qw, kw, HID);

    // tensor-core causal GQA flash attention -> g_ao_h
    flash_mma_kernel<<<dim3(NQH, SEQ / 128), 256, ATTN_SMEM>>>();

    // output projection: out[2048, 2560] = O @ Wo^T
    gemm_mma<<<dim3(HID / 128, SEQ / 128), 256, GEMM_SMEM>>>(
        ao_h, wo_h, out, QD, HID);
}